// round 2
// baseline (speedup 1.0000x reference)
#include <cuda_runtime.h>
#include <cuda_bf16.h>
#include <math.h>

// ---------------------------------------------------------------------------
// Problem constants
// ---------------------------------------------------------------------------
#define B_   4
#define S_   4096
#define T_   77
#define D_   1280
#define DT_  768
#define H_   8
#define HD_  160
#define RAD_ 64
#define M_BS (B_*S_)   // 16384
#define M_BT (B_*T_)   // 308
#define OFF_ ((size_t)M_BS * D_)

typedef __nv_bfloat16 bf16;

// ---------------------------------------------------------------------------
// Device scratch
// ---------------------------------------------------------------------------
__device__ float g_q  [M_BS * D_];
__device__ float g_Fg [M_BS * D_];
__device__ float g_F0 [M_BS * D_];
__device__ float g_F1 [M_BS * D_];
__device__ float g_k  [M_BT * D_];
__device__ float g_v  [M_BT * D_];

__device__ bf16 g_hs_hi [M_BS * D_];
__device__ bf16 g_hs_lo [M_BS * D_];
__device__ bf16 g_fg_hi [M_BS * D_];
__device__ bf16 g_fg_lo [M_BS * D_];
__device__ bf16 g_enc_hi[M_BT * DT_];
__device__ bf16 g_enc_lo[M_BT * DT_];
__device__ bf16 g_wq_hi [D_ * D_];
__device__ bf16 g_wq_lo [D_ * D_];
__device__ bf16 g_wo_hi [D_ * D_];
__device__ bf16 g_wo_lo [D_ * D_];
__device__ bf16 g_wk_hi [D_ * DT_];
__device__ bf16 g_wk_lo [D_ * DT_];
__device__ bf16 g_wv_hi [D_ * DT_];
__device__ bf16 g_wv_lo [D_ * DT_];

// ---------------------------------------------------------------------------
// fp32 -> bf16 hi/lo split helpers
// ---------------------------------------------------------------------------
__device__ __forceinline__ void split_bf16(float x, bf16& hi, bf16& lo) {
    hi = __float2bfloat16(x);
    lo = __float2bfloat16(x - __bfloat162float(hi));
}

// elementwise convert, 4 floats / thread
__global__ void convert_kernel(const float* __restrict__ x,
                               bf16* __restrict__ hi, bf16* __restrict__ lo, int n)
{
    int i = (blockIdx.x * 256 + threadIdx.x) * 4;
    if (i + 3 >= n) {
        for (int j = i; j < n; j++) { bf16 h, l; split_bf16(x[j], h, l); hi[j] = h; lo[j] = l; }
        return;
    }
    float4 v = *(const float4*)(x + i);
    bf16 h0,l0,h1,l1,h2,l2,h3,l3;
    split_bf16(v.x,h0,l0); split_bf16(v.y,h1,l1); split_bf16(v.z,h2,l2); split_bf16(v.w,h3,l3);
    hi[i]=h0; hi[i+1]=h1; hi[i+2]=h2; hi[i+3]=h3;
    lo[i]=l0; lo[i+1]=l1; lo[i+2]=l2; lo[i+3]=l3;
}

// fold LoRA into weight, output bf16 hi/lo
__global__ void fold_bf16_kernel(const float* __restrict__ W, const float* __restrict__ A,
                                 const float* __restrict__ Bm,
                                 bf16* __restrict__ hi, bf16* __restrict__ lo,
                                 int N, int K)
{
    int i = blockIdx.x * 256 + threadIdx.x;
    if (i >= N * K) return;
    int n = i / K;
    int k = i - n * K;
    float acc = W[i];
#pragma unroll
    for (int r = 0; r < 4; r++)
        acc += 0.25f * Bm[n * 4 + r] * A[r * K + k];
    bf16 h, l; split_bf16(acc, h, l);
    hi[i] = h; lo[i] = l;
}

// ---------------------------------------------------------------------------
// Tensor-core GEMM:  C[M,N] = A[M,K] @ W[N,K]^T  (+bias), fp32 via bf16 hi/lo
// BM=BN=128, BK=32, 256 threads (8 warps: 4m x 2n), warp tile 32x64.
// ---------------------------------------------------------------------------
#define SMS 40   // smem row stride in bf16 (32 + 8 pad)

__device__ __forceinline__ unsigned smem_u32(const void* p) {
    return (unsigned)__cvta_generic_to_shared(p);
}
__device__ __forceinline__ void ldmx4(unsigned& r0, unsigned& r1, unsigned& r2, unsigned& r3, unsigned addr) {
    asm volatile("ldmatrix.sync.aligned.m8n8.x4.shared.b16 {%0,%1,%2,%3}, [%4];"
                 : "=r"(r0), "=r"(r1), "=r"(r2), "=r"(r3) : "r"(addr));
}
__device__ __forceinline__ void mma_bf16(float* d, const unsigned* a, const unsigned* b) {
    asm volatile(
        "mma.sync.aligned.m16n8k16.row.col.f32.bf16.bf16.f32 "
        "{%0,%1,%2,%3}, {%4,%5,%6,%7}, {%8,%9}, {%0,%1,%2,%3};"
        : "+f"(d[0]), "+f"(d[1]), "+f"(d[2]), "+f"(d[3])
        : "r"(a[0]), "r"(a[1]), "r"(a[2]), "r"(a[3]), "r"(b[0]), "r"(b[1]));
}

__global__ void __launch_bounds__(256, 1) mma_gemm_kernel(
    const bf16* __restrict__ Ahi, const bf16* __restrict__ Alo,
    const bf16* __restrict__ Bhi, const bf16* __restrict__ Blo,
    const float* __restrict__ bias, float* __restrict__ C,
    int M, int N, int K)
{
    __shared__ bf16 sm[4 * 128 * SMS];
    bf16* As_hi = sm;
    bf16* As_lo = sm + 128 * SMS;
    bf16* Bs_hi = sm + 2 * 128 * SMS;
    bf16* Bs_lo = sm + 3 * 128 * SMS;

    const int tid  = threadIdx.x;
    const int warp = tid >> 5;
    const int lane = tid & 31;
    const int bm = blockIdx.y * 128;
    const int bn = blockIdx.x * 128;
    const int wm = (warp >> 1) * 32;   // warp m offset in tile
    const int wn = (warp & 1) * 64;    // warp n offset in tile

    // global load mapping: chunk c in [0,512): row=c>>2, koff=(c&3)*8
    const int c0 = tid, c1 = tid + 256;
    const int ar0 = c0 >> 2, ak0 = (c0 & 3) * 8;
    const int ar1 = c1 >> 2, ak1 = (c1 & 3) * 8;

    // ldmatrix shared addresses (ks=0); +32 bytes for ks=1
    unsigned a_addr[2], b_addr[4];
#pragma unroll
    for (int i = 0; i < 2; i++) {
        int row = wm + i * 16 + (lane & 15);
        int ko  = (lane >> 4) * 8;
        a_addr[i] = smem_u32(&As_hi[row * SMS + ko]);
    }
#pragma unroll
    for (int jp = 0; jp < 4; jp++) {
        int grp = lane >> 3, lr = lane & 7;
        int row = wn + jp * 16 + ((grp >> 1) * 8) + lr;
        int ko  = (grp & 1) * 8;
        b_addr[jp] = smem_u32(&Bs_hi[row * SMS + ko]);
    }
    const unsigned lo_off = (unsigned)(128 * SMS * sizeof(bf16)); // As_lo = As_hi + lo_off
    const unsigned b_lo_off = lo_off;                             // Bs_lo = Bs_hi + lo_off

    float acc[2][8][4];
#pragma unroll
    for (int i = 0; i < 2; i++)
#pragma unroll
        for (int j = 0; j < 8; j++)
#pragma unroll
            for (int r = 0; r < 4; r++) acc[i][j][r] = 0.f;

    const int KT = K >> 5;

    uint4 pah0, pal0, pah1, pal1, pbh0, pbl0, pbh1, pbl1;

    // prefetch tile 0
    {
        int gm0 = bm + ar0, gm1 = bm + ar1;
        pah0 = make_uint4(0,0,0,0); pal0 = pah0; pah1 = pah0; pal1 = pah0;
        if (gm0 < M) { pah0 = *(const uint4*)(Ahi + (size_t)gm0 * K + ak0);
                       pal0 = *(const uint4*)(Alo + (size_t)gm0 * K + ak0); }
        if (gm1 < M) { pah1 = *(const uint4*)(Ahi + (size_t)gm1 * K + ak1);
                       pal1 = *(const uint4*)(Alo + (size_t)gm1 * K + ak1); }
        pbh0 = *(const uint4*)(Bhi + (size_t)(bn + ar0) * K + ak0);
        pbl0 = *(const uint4*)(Blo + (size_t)(bn + ar0) * K + ak0);
        pbh1 = *(const uint4*)(Bhi + (size_t)(bn + ar1) * K + ak1);
        pbl1 = *(const uint4*)(Blo + (size_t)(bn + ar1) * K + ak1);
    }

    for (int kt = 0; kt < KT; kt++) {
        // store prefetched regs to smem
        *(uint4*)(As_hi + ar0 * SMS + ak0) = pah0;
        *(uint4*)(As_lo + ar0 * SMS + ak0) = pal0;
        *(uint4*)(As_hi + ar1 * SMS + ak1) = pah1;
        *(uint4*)(As_lo + ar1 * SMS + ak1) = pal1;
        *(uint4*)(Bs_hi + ar0 * SMS + ak0) = pbh0;
        *(uint4*)(Bs_lo + ar0 * SMS + ak0) = pbl0;
        *(uint4*)(Bs_hi + ar1 * SMS + ak1) = pbh1;
        *(uint4*)(Bs_lo + ar1 * SMS + ak1) = pbl1;
        __syncthreads();

        // prefetch next tile
        if (kt + 1 < KT) {
            int kbase = (kt + 1) * 32;
            int gm0 = bm + ar0, gm1 = bm + ar1;
            pah0 = make_uint4(0,0,0,0); pal0 = pah0; pah1 = pah0; pal1 = pah0;
            if (gm0 < M) { pah0 = *(const uint4*)(Ahi + (size_t)gm0 * K + kbase + ak0);
                           pal0 = *(const uint4*)(Alo + (size_t)gm0 * K + kbase + ak0); }
            if (gm1 < M) { pah1 = *(const uint4*)(Ahi + (size_t)gm1 * K + kbase + ak1);
                           pal1 = *(const uint4*)(Alo + (size_t)gm1 * K + kbase + ak1); }
            pbh0 = *(const uint4*)(Bhi + (size_t)(bn + ar0) * K + kbase + ak0);
            pbl0 = *(const uint4*)(Blo + (size_t)(bn + ar0) * K + kbase + ak0);
            pbh1 = *(const uint4*)(Bhi + (size_t)(bn + ar1) * K + kbase + ak1);
            pbl1 = *(const uint4*)(Blo + (size_t)(bn + ar1) * K + kbase + ak1);
        }

        // compute 2 k16 substeps
#pragma unroll
        for (int ks = 0; ks < 2; ks++) {
            unsigned kso = ks * 32;  // 16 bf16 = 32 bytes
            unsigned ah[2][4], al[2][4], bh[8][2], bl[8][2];
#pragma unroll
            for (int i = 0; i < 2; i++) {
                ldmx4(ah[i][0], ah[i][1], ah[i][2], ah[i][3], a_addr[i] + kso);
                ldmx4(al[i][0], al[i][1], al[i][2], al[i][3], a_addr[i] + kso + lo_off);
            }
#pragma unroll
            for (int jp = 0; jp < 4; jp++) {
                ldmx4(bh[jp*2][0], bh[jp*2][1], bh[jp*2+1][0], bh[jp*2+1][1], b_addr[jp] + kso);
                ldmx4(bl[jp*2][0], bl[jp*2][1], bl[jp*2+1][0], bl[jp*2+1][1], b_addr[jp] + kso + b_lo_off);
            }
#pragma unroll
            for (int i = 0; i < 2; i++)
#pragma unroll
                for (int j = 0; j < 8; j++) {
                    mma_bf16(acc[i][j], ah[i], bh[j]);
                    mma_bf16(acc[i][j], ah[i], bl[j]);
                    mma_bf16(acc[i][j], al[i], bh[j]);
                }
        }
        __syncthreads();
    }

    // epilogue
#pragma unroll
    for (int i = 0; i < 2; i++) {
        int r0 = bm + wm + i * 16 + (lane >> 2);
#pragma unroll
        for (int j = 0; j < 8; j++) {
            int col = bn + wn + j * 8 + (lane & 3) * 2;
            float b0 = bias ? bias[col] : 0.f;
            float b1 = bias ? bias[col + 1] : 0.f;
            if (r0 < M) {
                float2 v = make_float2(acc[i][j][0] + b0, acc[i][j][1] + b1);
                *(float2*)(C + (size_t)r0 * N + col) = v;
            }
            if (r0 + 8 < M) {
                float2 v = make_float2(acc[i][j][2] + b0, acc[i][j][3] + b1);
                *(float2*)(C + (size_t)(r0 + 8) * N + col) = v;
            }
        }
    }
}

// ---------------------------------------------------------------------------
// Attention: one warp per query row, K/V staged in smem. (unchanged)
// ---------------------------------------------------------------------------
__global__ void __launch_bounds__(256) attn_kernel(
    const float* __restrict__ q, const float* __restrict__ k,
    const float* __restrict__ v, const int* __restrict__ toks,
    int Tkv, int maybe64, float* __restrict__ outF)
{
    extern __shared__ float sm[];
    float* Ks = sm;
    float* Vs = sm + Tkv * HD_;

    const int b  = blockIdx.z;
    const int h  = blockIdx.y;
    const int s0 = blockIdx.x * 64;
    const int tid = threadIdx.x;

    int is64 = 0;
    if (toks && maybe64)
        is64 = (toks[1] == 0 && toks[3] == 0 && toks[5] == 0 && toks[7] == 0);

    for (int i = tid; i < Tkv * HD_; i += 256) {
        int t = i / HD_;
        int d = i - t * HD_;
        int trow = t;
        if (toks) trow = is64 ? toks[2 * t] : toks[t];
        size_t gidx = ((size_t)b * T_ + trow) * D_ + h * HD_ + d;
        Ks[i] = k[gidx];
        Vs[i] = v[gidx];
    }
    __syncthreads();

    const int warp = tid >> 5;
    const int lane = tid & 31;
    const float scale = 0.07905694150420949f;
    const unsigned FULL = 0xffffffffu;

    for (int itq = 0; itq < 8; itq++) {
        int s = s0 + warp * 8 + itq;
        size_t base = ((size_t)b * S_ + s) * D_ + h * HD_;

        float qr[5];
#pragma unroll
        for (int j = 0; j < 5; j++) qr[j] = q[base + lane + 32 * j];

        float sc0 = 0.f, sc1 = 0.f, sc2 = 0.f;
        for (int t = 0; t < Tkv; t++) {
            float p = 0.f;
            const float* kr = Ks + t * HD_;
#pragma unroll
            for (int j = 0; j < 5; j++) p += qr[j] * kr[lane + 32 * j];
#pragma unroll
            for (int off = 16; off; off >>= 1)
                p += __shfl_xor_sync(FULL, p, off);
            float val = p * scale;
            if ((t & 31) == lane) {
                int slot = t >> 5;
                if      (slot == 0) sc0 = val;
                else if (slot == 1) sc1 = val;
                else                sc2 = val;
            }
        }

        float m = -1e30f;
        if (lane      < Tkv) m = fmaxf(m, sc0);
        if (32 + lane < Tkv) m = fmaxf(m, sc1);
        if (64 + lane < Tkv) m = fmaxf(m, sc2);
#pragma unroll
        for (int off = 16; off; off >>= 1)
            m = fmaxf(m, __shfl_xor_sync(FULL, m, off));

        float ssum;
        sc0 = (lane      < Tkv) ? expf(sc0 - m) : 0.f;
        sc1 = (32 + lane < Tkv) ? expf(sc1 - m) : 0.f;
        sc2 = (64 + lane < Tkv) ? expf(sc2 - m) : 0.f;
        ssum = sc0 + sc1 + sc2;
#pragma unroll
        for (int off = 16; off; off >>= 1)
            ssum += __shfl_xor_sync(FULL, ssum, off);
        float inv = 1.f / ssum;
        sc0 *= inv; sc1 *= inv; sc2 *= inv;

        float o[5] = {0.f, 0.f, 0.f, 0.f, 0.f};
        for (int t = 0; t < Tkv; t++) {
            float src = (t < 32) ? sc0 : ((t < 64) ? sc1 : sc2);
            float p = __shfl_sync(FULL, src, t & 31);
            const float* vr = Vs + t * HD_;
#pragma unroll
            for (int j = 0; j < 5; j++) o[j] += p * vr[lane + 32 * j];
        }
#pragma unroll
        for (int j = 0; j < 5; j++) outF[base + lane + 32 * j] = o[j];
    }
}

// ---------------------------------------------------------------------------
// Feature adapter (unchanged)
// ---------------------------------------------------------------------------
#define RPB 8
__global__ void __launch_bounds__(256) adapter_kernel(
    const float* __restrict__ x,
    const float* __restrict__ dW, const float* __restrict__ db,
    const float* __restrict__ uW, const float* __restrict__ ub,
    float* __restrict__ out)
{
    __shared__ float xs[RPB][D_];
    __shared__ float hb[RPB][RAD_];

    const size_t row0 = (size_t)blockIdx.x * RPB;
    const int tid = threadIdx.x;
    const unsigned FULL = 0xffffffffu;

    for (int i = tid; i < RPB * D_; i += 256) {
        int r = i / D_;
        int d = i - r * D_;
        xs[r][d] = x[(row0 + r) * D_ + d];
    }
    __syncthreads();

    const int warp = tid >> 5;
    const int lane = tid & 31;

    for (int j = warp; j < RAD_; j += 8) {
        const float* w = dW + (size_t)j * D_;
        float ps[RPB];
#pragma unroll
        for (int r = 0; r < RPB; r++) ps[r] = 0.f;
        for (int i = lane; i < D_; i += 32) {
            float wv = w[i];
#pragma unroll
            for (int r = 0; r < RPB; r++) ps[r] += xs[r][i] * wv;
        }
#pragma unroll
        for (int r = 0; r < RPB; r++) {
#pragma unroll
            for (int off = 16; off; off >>= 1)
                ps[r] += __shfl_xor_sync(FULL, ps[r], off);
        }
        if (lane == 0) {
            float dbj = db[j];
#pragma unroll
            for (int r = 0; r < RPB; r++) {
                float hv = ps[r] + dbj;
                hb[r][j] = 0.5f * hv * (1.f + erff(hv * 0.7071067811865475f));
            }
        }
    }
    __syncthreads();

    for (int d = tid; d < D_; d += 256) {
        float o[RPB];
        float ubd = ub[d];
#pragma unroll
        for (int r = 0; r < RPB; r++) o[r] = xs[r][d] + ubd;
        const float* uwp = uW + (size_t)d * RAD_;
#pragma unroll 16
        for (int j = 0; j < RAD_; j++) {
            float uv = uwp[j];
#pragma unroll
            for (int r = 0; r < RPB; r++) o[r] += hb[r][j] * uv;
        }
#pragma unroll
        for (int r = 0; r < RPB; r++) out[(row0 + r) * D_ + d] = o[r];
    }
}

// ---------------------------------------------------------------------------
// Launch
// ---------------------------------------------------------------------------
extern "C" void kernel_launch(void* const* d_in, const int* in_sizes, int n_in,
                              void* d_out, int out_size)
{
    const float* hs    = (const float*)d_in[0];
    const float* enc   = (const float*)d_in[1];
    const int*   e0    = (const int*)  d_in[2];
    const int*   e1    = (const int*)  d_in[3];
    const float* Wq    = (const float*)d_in[4];
    const float* Wk    = (const float*)d_in[5];
    const float* Wv    = (const float*)d_in[6];
    const float* Wo    = (const float*)d_in[7];
    const float* bo    = (const float*)d_in[8];
    const float* lkA   = (const float*)d_in[9];
    const float* lkB   = (const float*)d_in[10];
    const float* lvA   = (const float*)d_in[11];
    const float* lvB   = (const float*)d_in[12];
    const float* loA   = (const float*)d_in[13];
    const float* loB   = (const float*)d_in[14];
    const float* a0dW  = (const float*)d_in[15];
    const float* a0db  = (const float*)d_in[16];
    const float* a0uW  = (const float*)d_in[17];
    const float* a0ub  = (const float*)d_in[18];
    const float* a1dW  = (const float*)d_in[19];
    const float* a1db  = (const float*)d_in[20];
    const float* a1uW  = (const float*)d_in[21];
    const float* a1ub  = (const float*)d_in[22];

    float *qp, *fgp, *f0p, *f1p, *kp, *vp;
    bf16 *hsh, *hsl, *fgh, *fgl, *ench, *encl;
    bf16 *wqh, *wql, *woh, *wol, *wkh, *wkl, *wvh, *wvl;
    cudaGetSymbolAddress((void**)&qp,   g_q);
    cudaGetSymbolAddress((void**)&fgp,  g_Fg);
    cudaGetSymbolAddress((void**)&f0p,  g_F0);
    cudaGetSymbolAddress((void**)&f1p,  g_F1);
    cudaGetSymbolAddress((void**)&kp,   g_k);
    cudaGetSymbolAddress((void**)&vp,   g_v);
    cudaGetSymbolAddress((void**)&hsh,  g_hs_hi);
    cudaGetSymbolAddress((void**)&hsl,  g_hs_lo);
    cudaGetSymbolAddress((void**)&fgh,  g_fg_hi);
    cudaGetSymbolAddress((void**)&fgl,  g_fg_lo);
    cudaGetSymbolAddress((void**)&ench, g_enc_hi);
    cudaGetSymbolAddress((void**)&encl, g_enc_lo);
    cudaGetSymbolAddress((void**)&wqh,  g_wq_hi);
    cudaGetSymbolAddress((void**)&wql,  g_wq_lo);
    cudaGetSymbolAddress((void**)&woh,  g_wo_hi);
    cudaGetSymbolAddress((void**)&wol,  g_wo_lo);
    cudaGetSymbolAddress((void**)&wkh,  g_wk_hi);
    cudaGetSymbolAddress((void**)&wkl,  g_wk_lo);
    cudaGetSymbolAddress((void**)&wvh,  g_wv_hi);
    cudaGetSymbolAddress((void**)&wvl,  g_wv_lo);

    float* out = (float*)d_out;

    // 1) conversions + LoRA folds (all emit bf16 hi/lo)
    convert_kernel<<<(M_BS * D_ / 4 + 255) / 256, 256>>>(hs,  hsh,  hsl,  M_BS * D_);
    convert_kernel<<<(M_BT * DT_ / 4 + 255) / 256, 256>>>(enc, ench, encl, M_BT * DT_);
    convert_kernel<<<(D_ * D_ / 4 + 255) / 256, 256>>>(Wq, wqh, wql, D_ * D_);
    fold_bf16_kernel<<<(D_ * DT_ + 255) / 256, 256>>>(Wk, lkA, lkB, wkh, wkl, D_, DT_);
    fold_bf16_kernel<<<(D_ * DT_ + 255) / 256, 256>>>(Wv, lvA, lvB, wvh, wvl, D_, DT_);
    fold_bf16_kernel<<<(D_ * D_  + 255) / 256, 256>>>(Wo, loA, loB, woh, wol, D_, D_);

    // 2) k, v projections
    dim3 gkv(D_ / 128, (M_BT + 127) / 128);
    mma_gemm_kernel<<<gkv, 256>>>(ench, encl, wkh, wkl, nullptr, kp, M_BT, D_, DT_);
    mma_gemm_kernel<<<gkv, 256>>>(ench, encl, wvh, wvl, nullptr, vp, M_BT, D_, DT_);

    // 3) q projection
    dim3 gq(D_ / 128, M_BS / 128);
    mma_gemm_kernel<<<gq, 256>>>(hsh, hsl, wqh, wql, nullptr, qp, M_BS, D_, D_);

    // 4) attention
    cudaFuncSetAttribute(attn_kernel,
                         cudaFuncAttributeMaxDynamicSharedMemorySize, 101376);
    dim3 ga(S_ / 64, H_, B_);
    attn_kernel<<<ga, 256, (size_t)T_ * HD_ * 2 * sizeof(float)>>>(
        qp, kp, vp, nullptr, T_, 0, fgp);
    attn_kernel<<<ga, 256, (size_t)8 * HD_ * 2 * sizeof(float)>>>(
        qp, kp, vp, e0, 8, 1, f0p);
    attn_kernel<<<ga, 256, (size_t)12 * HD_ * 2 * sizeof(float)>>>(
        qp, kp, vp, e1, 12, 0, f1p);

    // 5) adapters
    adapter_kernel<<<M_BS / RPB, 256>>>(f0p, a0dW, a0db, a0uW, a0ub, out + OFF_);
    adapter_kernel<<<M_BS / RPB, 256>>>(f1p, a1dW, a1db, a1uW, a1ub, out + 2 * OFF_);

    // 6) convert F_g and output projection
    convert_kernel<<<(M_BS * D_ / 4 + 255) / 256, 256>>>(fgp, fgh, fgl, M_BS * D_);
    mma_gemm_kernel<<<gq, 256>>>(fgh, fgl, woh, wol, bo, out, M_BS, D_, D_);
}

// round 3
// speedup vs baseline: 1.6055x; 1.6055x over previous
#include <cuda_runtime.h>
#include <cuda_bf16.h>
#include <math.h>

// ---------------------------------------------------------------------------
// Problem constants
// ---------------------------------------------------------------------------
#define B_   4
#define S_   4096
#define T_   77
#define D_   1280
#define DT_  768
#define H_   8
#define HD_  160
#define RAD_ 64
#define M_BS (B_*S_)   // 16384
#define M_BT (B_*T_)   // 308
#define OFF_ ((size_t)M_BS * D_)

typedef __nv_bfloat16 bf16;

// ---------------------------------------------------------------------------
// Device scratch
// ---------------------------------------------------------------------------
__device__ float g_q  [M_BS * D_];
__device__ float g_Fg [M_BS * D_];
__device__ float g_F0 [M_BS * D_];
__device__ float g_F1 [M_BS * D_];
__device__ float g_k  [M_BT * D_];
__device__ float g_v  [M_BT * D_];

__device__ bf16 g_hs_hi [M_BS * D_];
__device__ bf16 g_hs_lo [M_BS * D_];
__device__ bf16 g_fg_hi [M_BS * D_];
__device__ bf16 g_fg_lo [M_BS * D_];
__device__ bf16 g_enc_hi[M_BT * DT_];
__device__ bf16 g_enc_lo[M_BT * DT_];
__device__ bf16 g_wq_hi [D_ * D_];
__device__ bf16 g_wq_lo [D_ * D_];
__device__ bf16 g_wo_hi [D_ * D_];
__device__ bf16 g_wo_lo [D_ * D_];
__device__ bf16 g_wk_hi [D_ * DT_];
__device__ bf16 g_wk_lo [D_ * DT_];
__device__ bf16 g_wv_hi [D_ * DT_];
__device__ bf16 g_wv_lo [D_ * DT_];

// ---------------------------------------------------------------------------
// fp32 -> bf16 hi/lo split helpers
// ---------------------------------------------------------------------------
__device__ __forceinline__ void split_bf16(float x, bf16& hi, bf16& lo) {
    hi = __float2bfloat16(x);
    lo = __float2bfloat16(x - __bfloat162float(hi));
}

__global__ void convert_kernel(const float* __restrict__ x,
                               bf16* __restrict__ hi, bf16* __restrict__ lo, int n)
{
    int i = (blockIdx.x * 256 + threadIdx.x) * 4;
    if (i + 3 >= n) {
        for (int j = i; j < n; j++) { bf16 h, l; split_bf16(x[j], h, l); hi[j] = h; lo[j] = l; }
        return;
    }
    float4 v = *(const float4*)(x + i);
    bf16 h0,l0,h1,l1,h2,l2,h3,l3;
    split_bf16(v.x,h0,l0); split_bf16(v.y,h1,l1); split_bf16(v.z,h2,l2); split_bf16(v.w,h3,l3);
    hi[i]=h0; hi[i+1]=h1; hi[i+2]=h2; hi[i+3]=h3;
    lo[i]=l0; lo[i+1]=l1; lo[i+2]=l2; lo[i+3]=l3;
}

__global__ void fold_bf16_kernel(const float* __restrict__ W, const float* __restrict__ A,
                                 const float* __restrict__ Bm,
                                 bf16* __restrict__ hi, bf16* __restrict__ lo,
                                 int N, int K)
{
    int i = blockIdx.x * 256 + threadIdx.x;
    if (i >= N * K) return;
    int n = i / K;
    int k = i - n * K;
    float acc = W[i];
#pragma unroll
    for (int r = 0; r < 4; r++)
        acc += 0.25f * Bm[n * 4 + r] * A[r * K + k];
    bf16 h, l; split_bf16(acc, h, l);
    hi[i] = h; lo[i] = l;
}

// ---------------------------------------------------------------------------
// Tensor-core GEMM:  C[M,N] = A[M,K] @ W[N,K]^T  (+bias), fp32 via bf16 hi/lo
// BM=BN=128, BK=32, 256 threads (8 warps: 4m x 2n), warp tile 32x64.
// cp.async 2-stage double buffer; one __syncthreads per K-tile.
// ---------------------------------------------------------------------------
#define SMS 40   // smem row stride in bf16 (32 data + 8 pad) -> 80B rows

__device__ __forceinline__ unsigned smem_u32(const void* p) {
    return (unsigned)__cvta_generic_to_shared(p);
}
__device__ __forceinline__ void ldmx4(unsigned& r0, unsigned& r1, unsigned& r2, unsigned& r3, unsigned addr) {
    asm volatile("ldmatrix.sync.aligned.m8n8.x4.shared.b16 {%0,%1,%2,%3}, [%4];"
                 : "=r"(r0), "=r"(r1), "=r"(r2), "=r"(r3) : "r"(addr));
}
__device__ __forceinline__ void mma_bf16(float* d, const unsigned* a, const unsigned* b) {
    asm volatile(
        "mma.sync.aligned.m16n8k16.row.col.f32.bf16.bf16.f32 "
        "{%0,%1,%2,%3}, {%4,%5,%6,%7}, {%8,%9}, {%0,%1,%2,%3};"
        : "+f"(d[0]), "+f"(d[1]), "+f"(d[2]), "+f"(d[3])
        : "r"(a[0]), "r"(a[1]), "r"(a[2]), "r"(a[3]), "r"(b[0]), "r"(b[1]));
}
__device__ __forceinline__ void cpa16(unsigned dst, const bf16* src, int sz) {
    asm volatile("cp.async.cg.shared.global [%0], [%1], 16, %2;\n"
                 :: "r"(dst), "l"(src), "r"(sz));
}

#define MATB  (128 * SMS * 2)   // bytes per matrix panel
#define STAGEB (4 * MATB)       // bytes per pipeline stage
#define GSMEM (2 * STAGEB)      // total dynamic smem (81920 B)

__global__ void __launch_bounds__(256, 1) mma_gemm_kernel(
    const bf16* __restrict__ Ahi, const bf16* __restrict__ Alo,
    const bf16* __restrict__ Bhi, const bf16* __restrict__ Blo,
    const float* __restrict__ bias, float* __restrict__ C,
    int M, int N, int K)
{
    extern __shared__ bf16 smem_dyn[];
    const unsigned sbase = smem_u32(smem_dyn);

    const int tid  = threadIdx.x;
    const int warp = tid >> 5;
    const int lane = tid & 31;
    const int bm = blockIdx.y * 128;
    const int bn = blockIdx.x * 128;
    const int wm = (warp >> 1) * 32;
    const int wn = (warp & 1) * 64;

    // global/smem load mapping: chunk c in [0,512): row=c>>2, ko=(c&3)*8 bf16
    const int c0 = tid, c1 = tid + 256;
    const int ar0 = c0 >> 2, ak0 = (c0 & 3) * 8;
    const int ar1 = c1 >> 2, ak1 = (c1 & 3) * 8;
    const int gm0 = bm + ar0, gm1 = bm + ar1;
    const int szA0 = (gm0 < M) ? 16 : 0;
    const int szA1 = (gm1 < M) ? 16 : 0;
    const size_t aoff0 = (size_t)gm0 * K + ak0;
    const size_t aoff1 = (size_t)gm1 * K + ak1;
    const size_t boff0 = (size_t)(bn + ar0) * K + ak0;
    const size_t boff1 = (size_t)(bn + ar1) * K + ak1;
    const unsigned dst0 = sbase + (unsigned)(ar0 * SMS + ak0) * 2;
    const unsigned dst1 = sbase + (unsigned)(ar1 * SMS + ak1) * 2;

    // ldmatrix base addresses (within stage 0; hi panels)
    unsigned a_addr[2], b_addr[4];
#pragma unroll
    for (int i = 0; i < 2; i++) {
        int row = wm + i * 16 + (lane & 15);
        int ko  = (lane >> 4) * 8;
        a_addr[i] = sbase + (unsigned)(row * SMS + ko) * 2;
    }
#pragma unroll
    for (int jp = 0; jp < 4; jp++) {
        int grp = lane >> 3, lr = lane & 7;
        int row = wn + jp * 16 + ((grp >> 1) * 8) + lr;
        int ko  = (grp & 1) * 8;
        b_addr[jp] = sbase + 2u * MATB + (unsigned)(row * SMS + ko) * 2;
    }

    float acc[2][8][4];
#pragma unroll
    for (int i = 0; i < 2; i++)
#pragma unroll
        for (int j = 0; j < 8; j++)
#pragma unroll
            for (int r = 0; r < 4; r++) acc[i][j][r] = 0.f;

    const int KT = K >> 5;

    // ---- load one stage's 8 chunks for K-tile kt into stage st ----
    auto load_stage = [&](int st, int kt) {
        const unsigned so = (unsigned)st * STAGEB;
        const int kb = kt * 32;
        cpa16(dst0 + so,            Ahi + aoff0 + kb, szA0);
        cpa16(dst1 + so,            Ahi + aoff1 + kb, szA1);
        cpa16(dst0 + so + MATB,     Alo + aoff0 + kb, szA0);
        cpa16(dst1 + so + MATB,     Alo + aoff1 + kb, szA1);
        cpa16(dst0 + so + 2u*MATB,  Bhi + boff0 + kb, 16);
        cpa16(dst1 + so + 2u*MATB,  Bhi + boff1 + kb, 16);
        cpa16(dst0 + so + 3u*MATB,  Blo + boff0 + kb, 16);
        cpa16(dst1 + so + 3u*MATB,  Blo + boff1 + kb, 16);
        asm volatile("cp.async.commit_group;\n");
    };

    load_stage(0, 0);

    for (int kt = 0; kt < KT; kt++) {
        asm volatile("cp.async.wait_group 0;\n");
        __syncthreads();

        if (kt + 1 < KT) load_stage((kt + 1) & 1, kt + 1);

        const unsigned so = (unsigned)(kt & 1) * STAGEB;
#pragma unroll
        for (int ks = 0; ks < 2; ks++) {
            const unsigned kso = so + ks * 32;
            unsigned ah[2][4], al[2][4];
#pragma unroll
            for (int i = 0; i < 2; i++) {
                ldmx4(ah[i][0], ah[i][1], ah[i][2], ah[i][3], a_addr[i] + kso);
                ldmx4(al[i][0], al[i][1], al[i][2], al[i][3], a_addr[i] + kso + MATB);
            }
#pragma unroll
            for (int jp = 0; jp < 4; jp++) {
                unsigned bh[2][2], bl[2][2];
                ldmx4(bh[0][0], bh[0][1], bh[1][0], bh[1][1], b_addr[jp] + kso);
                ldmx4(bl[0][0], bl[0][1], bl[1][0], bl[1][1], b_addr[jp] + kso + MATB);
                // pass-major ordering: consecutive MMAs hit different accumulators
#pragma unroll
                for (int jj = 0; jj < 2; jj++) {
                    int j = jp * 2 + jj;
                    mma_bf16(acc[0][j], ah[0], bh[jj]);
                    mma_bf16(acc[1][j], ah[1], bh[jj]);
                }
#pragma unroll
                for (int jj = 0; jj < 2; jj++) {
                    int j = jp * 2 + jj;
                    mma_bf16(acc[0][j], ah[0], bl[jj]);
                    mma_bf16(acc[1][j], ah[1], bl[jj]);
                }
#pragma unroll
                for (int jj = 0; jj < 2; jj++) {
                    int j = jp * 2 + jj;
                    mma_bf16(acc[0][j], al[0], bh[jj]);
                    mma_bf16(acc[1][j], al[1], bh[jj]);
                }
            }
        }
        __syncthreads();
    }

    // epilogue
#pragma unroll
    for (int i = 0; i < 2; i++) {
        int r0 = bm + wm + i * 16 + (lane >> 2);
#pragma unroll
        for (int j = 0; j < 8; j++) {
            int col = bn + wn + j * 8 + (lane & 3) * 2;
            float b0 = bias ? bias[col] : 0.f;
            float b1 = bias ? bias[col + 1] : 0.f;
            if (r0 < M) {
                float2 v = make_float2(acc[i][j][0] + b0, acc[i][j][1] + b1);
                *(float2*)(C + (size_t)r0 * N + col) = v;
            }
            if (r0 + 8 < M) {
                float2 v = make_float2(acc[i][j][2] + b0, acc[i][j][3] + b1);
                *(float2*)(C + (size_t)(r0 + 8) * N + col) = v;
            }
        }
    }
}

// ---------------------------------------------------------------------------
// Attention (unchanged)
// ---------------------------------------------------------------------------
__global__ void __launch_bounds__(256) attn_kernel(
    const float* __restrict__ q, const float* __restrict__ k,
    const float* __restrict__ v, const int* __restrict__ toks,
    int Tkv, int maybe64, float* __restrict__ outF)
{
    extern __shared__ float sm[];
    float* Ks = sm;
    float* Vs = sm + Tkv * HD_;

    const int b  = blockIdx.z;
    const int h  = blockIdx.y;
    const int s0 = blockIdx.x * 64;
    const int tid = threadIdx.x;

    int is64 = 0;
    if (toks && maybe64)
        is64 = (toks[1] == 0 && toks[3] == 0 && toks[5] == 0 && toks[7] == 0);

    for (int i = tid; i < Tkv * HD_; i += 256) {
        int t = i / HD_;
        int d = i - t * HD_;
        int trow = t;
        if (toks) trow = is64 ? toks[2 * t] : toks[t];
        size_t gidx = ((size_t)b * T_ + trow) * D_ + h * HD_ + d;
        Ks[i] = k[gidx];
        Vs[i] = v[gidx];
    }
    __syncthreads();

    const int warp = tid >> 5;
    const int lane = tid & 31;
    const float scale = 0.07905694150420949f;
    const unsigned FULL = 0xffffffffu;

    for (int itq = 0; itq < 8; itq++) {
        int s = s0 + warp * 8 + itq;
        size_t base = ((size_t)b * S_ + s) * D_ + h * HD_;

        float qr[5];
#pragma unroll
        for (int j = 0; j < 5; j++) qr[j] = q[base + lane + 32 * j];

        float sc0 = 0.f, sc1 = 0.f, sc2 = 0.f;
        for (int t = 0; t < Tkv; t++) {
            float p = 0.f;
            const float* kr = Ks + t * HD_;
#pragma unroll
            for (int j = 0; j < 5; j++) p += qr[j] * kr[lane + 32 * j];
#pragma unroll
            for (int off = 16; off; off >>= 1)
                p += __shfl_xor_sync(FULL, p, off);
            float val = p * scale;
            if ((t & 31) == lane) {
                int slot = t >> 5;
                if      (slot == 0) sc0 = val;
                else if (slot == 1) sc1 = val;
                else                sc2 = val;
            }
        }

        float m = -1e30f;
        if (lane      < Tkv) m = fmaxf(m, sc0);
        if (32 + lane < Tkv) m = fmaxf(m, sc1);
        if (64 + lane < Tkv) m = fmaxf(m, sc2);
#pragma unroll
        for (int off = 16; off; off >>= 1)
            m = fmaxf(m, __shfl_xor_sync(FULL, m, off));

        float ssum;
        sc0 = (lane      < Tkv) ? expf(sc0 - m) : 0.f;
        sc1 = (32 + lane < Tkv) ? expf(sc1 - m) : 0.f;
        sc2 = (64 + lane < Tkv) ? expf(sc2 - m) : 0.f;
        ssum = sc0 + sc1 + sc2;
#pragma unroll
        for (int off = 16; off; off >>= 1)
            ssum += __shfl_xor_sync(FULL, ssum, off);
        float inv = 1.f / ssum;
        sc0 *= inv; sc1 *= inv; sc2 *= inv;

        float o[5] = {0.f, 0.f, 0.f, 0.f, 0.f};
        for (int t = 0; t < Tkv; t++) {
            float src = (t < 32) ? sc0 : ((t < 64) ? sc1 : sc2);
            float p = __shfl_sync(FULL, src, t & 31);
            const float* vr = Vs + t * HD_;
#pragma unroll
            for (int j = 0; j < 5; j++) o[j] += p * vr[lane + 32 * j];
        }
#pragma unroll
        for (int j = 0; j < 5; j++) outF[base + lane + 32 * j] = o[j];
    }
}

// ---------------------------------------------------------------------------
// Feature adapter (unchanged)
// ---------------------------------------------------------------------------
#define RPB 8
__global__ void __launch_bounds__(256) adapter_kernel(
    const float* __restrict__ x,
    const float* __restrict__ dW, const float* __restrict__ db,
    const float* __restrict__ uW, const float* __restrict__ ub,
    float* __restrict__ out)
{
    __shared__ float xs[RPB][D_];
    __shared__ float hb[RPB][RAD_];

    const size_t row0 = (size_t)blockIdx.x * RPB;
    const int tid = threadIdx.x;
    const unsigned FULL = 0xffffffffu;

    for (int i = tid; i < RPB * D_; i += 256) {
        int r = i / D_;
        int d = i - r * D_;
        xs[r][d] = x[(row0 + r) * D_ + d];
    }
    __syncthreads();

    const int warp = tid >> 5;
    const int lane = tid & 31;

    for (int j = warp; j < RAD_; j += 8) {
        const float* w = dW + (size_t)j * D_;
        float ps[RPB];
#pragma unroll
        for (int r = 0; r < RPB; r++) ps[r] = 0.f;
        for (int i = lane; i < D_; i += 32) {
            float wv = w[i];
#pragma unroll
            for (int r = 0; r < RPB; r++) ps[r] += xs[r][i] * wv;
        }
#pragma unroll
        for (int r = 0; r < RPB; r++) {
#pragma unroll
            for (int off = 16; off; off >>= 1)
                ps[r] += __shfl_xor_sync(FULL, ps[r], off);
        }
        if (lane == 0) {
            float dbj = db[j];
#pragma unroll
            for (int r = 0; r < RPB; r++) {
                float hv = ps[r] + dbj;
                hb[r][j] = 0.5f * hv * (1.f + erff(hv * 0.7071067811865475f));
            }
        }
    }
    __syncthreads();

    for (int d = tid; d < D_; d += 256) {
        float o[RPB];
        float ubd = ub[d];
#pragma unroll
        for (int r = 0; r < RPB; r++) o[r] = xs[r][d] + ubd;
        const float* uwp = uW + (size_t)d * RAD_;
#pragma unroll 16
        for (int j = 0; j < RAD_; j++) {
            float uv = uwp[j];
#pragma unroll
            for (int r = 0; r < RPB; r++) o[r] += hb[r][j] * uv;
        }
#pragma unroll
        for (int r = 0; r < RPB; r++) out[(row0 + r) * D_ + d] = o[r];
    }
}

// ---------------------------------------------------------------------------
// Launch
// ---------------------------------------------------------------------------
extern "C" void kernel_launch(void* const* d_in, const int* in_sizes, int n_in,
                              void* d_out, int out_size)
{
    const float* hs    = (const float*)d_in[0];
    const float* enc   = (const float*)d_in[1];
    const int*   e0    = (const int*)  d_in[2];
    const int*   e1    = (const int*)  d_in[3];
    const float* Wq    = (const float*)d_in[4];
    const float* Wk    = (const float*)d_in[5];
    const float* Wv    = (const float*)d_in[6];
    const float* Wo    = (const float*)d_in[7];
    const float* bo    = (const float*)d_in[8];
    const float* lkA   = (const float*)d_in[9];
    const float* lkB   = (const float*)d_in[10];
    const float* lvA   = (const float*)d_in[11];
    const float* lvB   = (const float*)d_in[12];
    const float* loA   = (const float*)d_in[13];
    const float* loB   = (const float*)d_in[14];
    const float* a0dW  = (const float*)d_in[15];
    const float* a0db  = (const float*)d_in[16];
    const float* a0uW  = (const float*)d_in[17];
    const float* a0ub  = (const float*)d_in[18];
    const float* a1dW  = (const float*)d_in[19];
    const float* a1db  = (const float*)d_in[20];
    const float* a1uW  = (const float*)d_in[21];
    const float* a1ub  = (const float*)d_in[22];

    float *qp, *fgp, *f0p, *f1p, *kp, *vp;
    bf16 *hsh, *hsl, *fgh, *fgl, *ench, *encl;
    bf16 *wqh, *wql, *woh, *wol, *wkh, *wkl, *wvh, *wvl;
    cudaGetSymbolAddress((void**)&qp,   g_q);
    cudaGetSymbolAddress((void**)&fgp,  g_Fg);
    cudaGetSymbolAddress((void**)&f0p,  g_F0);
    cudaGetSymbolAddress((void**)&f1p,  g_F1);
    cudaGetSymbolAddress((void**)&kp,   g_k);
    cudaGetSymbolAddress((void**)&vp,   g_v);
    cudaGetSymbolAddress((void**)&hsh,  g_hs_hi);
    cudaGetSymbolAddress((void**)&hsl,  g_hs_lo);
    cudaGetSymbolAddress((void**)&fgh,  g_fg_hi);
    cudaGetSymbolAddress((void**)&fgl,  g_fg_lo);
    cudaGetSymbolAddress((void**)&ench, g_enc_hi);
    cudaGetSymbolAddress((void**)&encl, g_enc_lo);
    cudaGetSymbolAddress((void**)&wqh,  g_wq_hi);
    cudaGetSymbolAddress((void**)&wql,  g_wq_lo);
    cudaGetSymbolAddress((void**)&woh,  g_wo_hi);
    cudaGetSymbolAddress((void**)&wol,  g_wo_lo);
    cudaGetSymbolAddress((void**)&wkh,  g_wk_hi);
    cudaGetSymbolAddress((void**)&wkl,  g_wk_lo);
    cudaGetSymbolAddress((void**)&wvh,  g_wv_hi);
    cudaGetSymbolAddress((void**)&wvl,  g_wv_lo);

    float* out = (float*)d_out;

    cudaFuncSetAttribute(mma_gemm_kernel,
                         cudaFuncAttributeMaxDynamicSharedMemorySize, GSMEM);
    cudaFuncSetAttribute(attn_kernel,
                         cudaFuncAttributeMaxDynamicSharedMemorySize, 101376);

    // launches 1-5: conversions + kv folds
    convert_kernel<<<(M_BS * D_ / 4 + 255) / 256, 256>>>(hs,  hsh,  hsl,  M_BS * D_);
    convert_kernel<<<(M_BT * DT_ / 4 + 255) / 256, 256>>>(enc, ench, encl, M_BT * DT_);
    convert_kernel<<<(D_ * D_ / 4 + 255) / 256, 256>>>(Wq, wqh, wql, D_ * D_);
    fold_bf16_kernel<<<(D_ * DT_ + 255) / 256, 256>>>(Wk, lkA, lkB, wkh, wkl, D_, DT_);
    fold_bf16_kernel<<<(D_ * DT_ + 255) / 256, 256>>>(Wv, lvA, lvB, wvh, wvl, D_, DT_);

    // launch 6: q projection  (this is what ncu -s 5 -c 1 captures)
    dim3 gq(D_ / 128, M_BS / 128);
    mma_gemm_kernel<<<gq, 256, GSMEM>>>(hsh, hsl, wqh, wql, nullptr, qp, M_BS, D_, D_);

    // fold Wo (independent)
    fold_bf16_kernel<<<(D_ * D_  + 255) / 256, 256>>>(Wo, loA, loB, woh, wol, D_, D_);

    // k, v projections
    dim3 gkv(D_ / 128, (M_BT + 127) / 128);
    mma_gemm_kernel<<<gkv, 256, GSMEM>>>(ench, encl, wkh, wkl, nullptr, kp, M_BT, D_, DT_);
    mma_gemm_kernel<<<gkv, 256, GSMEM>>>(ench, encl, wvh, wvl, nullptr, vp, M_BT, D_, DT_);

    // attention
    dim3 ga(S_ / 64, H_, B_);
    attn_kernel<<<ga, 256, (size_t)T_ * HD_ * 2 * sizeof(float)>>>(
        qp, kp, vp, nullptr, T_, 0, fgp);
    attn_kernel<<<ga, 256, (size_t)8 * HD_ * 2 * sizeof(float)>>>(
        qp, kp, vp, e0, 8, 1, f0p);
    attn_kernel<<<ga, 256, (size_t)12 * HD_ * 2 * sizeof(float)>>>(
        qp, kp, vp, e1, 12, 0, f1p);

    // adapters
    adapter_kernel<<<M_BS / RPB, 256>>>(f0p, a0dW, a0db, a0uW, a0ub, out + OFF_);
    adapter_kernel<<<M_BS / RPB, 256>>>(f1p, a1dW, a1db, a1uW, a1ub, out + 2 * OFF_);

    // F_g convert + output projection
    convert_kernel<<<(M_BS * D_ / 4 + 255) / 256, 256>>>(fgp, fgh, fgl, M_BS * D_);
    mma_gemm_kernel<<<gq, 256, GSMEM>>>(fgh, fgl, woh, wol, bo, out, M_BS, D_, D_);
}

// round 7
// speedup vs baseline: 1.8495x; 1.1519x over previous
#include <cuda_runtime.h>
#include <cuda_fp16.h>
#include <math.h>
#include <stdint.h>
#include <stddef.h>

// ---------------------------------------------------------------------------
// Problem constants
// ---------------------------------------------------------------------------
#define B_   4
#define S_   4096
#define T_   77
#define D_   1280
#define DT_  768
#define H_   8
#define HD_  160
#define RAD_ 64
#define M_BS (B_*S_)   // 16384
#define M_BT (B_*T_)   // 308
#define OFF_ ((size_t)M_BS * D_)

typedef __half fp16;

// ---------------------------------------------------------------------------
// Device scratch
// ---------------------------------------------------------------------------
__device__ float g_q  [M_BS * D_];
__device__ float g_Fg [M_BS * D_];
__device__ float g_F0 [M_BS * D_];
__device__ float g_F1 [M_BS * D_];
__device__ float g_k  [M_BT * D_];
__device__ float g_v  [M_BT * D_];

__device__ fp16 g_hs_hi [M_BS * D_];
__device__ fp16 g_hs_lo [M_BS * D_];
__device__ fp16 g_fg_hi [M_BS * D_];
__device__ fp16 g_fg_lo [M_BS * D_];
__device__ fp16 g_enc_hi[M_BT * DT_];
__device__ fp16 g_enc_lo[M_BT * DT_];
__device__ fp16 g_wq [D_ * D_];
__device__ fp16 g_wo [D_ * D_];
__device__ fp16 g_wk [D_ * DT_];
__device__ fp16 g_wv [D_ * DT_];

// ---------------------------------------------------------------------------
// helpers
// ---------------------------------------------------------------------------
__device__ __forceinline__ unsigned smem_u32(const void* p) {
    return (unsigned)__cvta_generic_to_shared(p);
}
__device__ __forceinline__ void cpa16(unsigned dst, const fp16* src, int sz) {
    asm volatile("cp.async.cg.shared.global [%0], [%1], 16, %2;\n"
                 :: "r"(dst), "l"(src), "r"(sz));
}
__device__ __forceinline__ void ldmx4(unsigned& r0, unsigned& r1, unsigned& r2, unsigned& r3, unsigned addr) {
    asm volatile("ldmatrix.sync.aligned.m8n8.x4.shared.b16 {%0,%1,%2,%3}, [%4];"
                 : "=r"(r0), "=r"(r1), "=r"(r2), "=r"(r3) : "r"(addr));
}
__device__ __forceinline__ void mma_f16(float* d, const unsigned* a, const unsigned* b) {
    asm volatile(
        "mma.sync.aligned.m16n8k16.row.col.f32.f16.f16.f32 "
        "{%0,%1,%2,%3}, {%4,%5,%6,%7}, {%8,%9}, {%0,%1,%2,%3};"
        : "+f"(d[0]), "+f"(d[1]), "+f"(d[2]), "+f"(d[3])
        : "r"(a[0]), "r"(a[1]), "r"(a[2]), "r"(a[3]), "r"(b[0]), "r"(b[1]));
}

__device__ __forceinline__ void split_f16(float x, fp16& hi, fp16& lo) {
    hi = __float2half_rn(x);
    lo = __float2half_rn(x - __half2float(hi));
}

// fp32 -> fp16 hi/lo (activations)
__global__ void convert2_kernel(const float* __restrict__ x,
                                fp16* __restrict__ hi, fp16* __restrict__ lo, int n)
{
    int i = (blockIdx.x * 256 + threadIdx.x) * 4;
    if (i + 3 >= n) {
        for (int j = i; j < n; j++) { fp16 h, l; split_f16(x[j], h, l); hi[j] = h; lo[j] = l; }
        return;
    }
    float4 v = *(const float4*)(x + i);
    fp16 h0,l0,h1,l1,h2,l2,h3,l3;
    split_f16(v.x,h0,l0); split_f16(v.y,h1,l1); split_f16(v.z,h2,l2); split_f16(v.w,h3,l3);
    hi[i]=h0; hi[i+1]=h1; hi[i+2]=h2; hi[i+3]=h3;
    lo[i]=l0; lo[i+1]=l1; lo[i+2]=l2; lo[i+3]=l3;
}

// fp32 -> fp16 single (weights)
__global__ void convertw_kernel(const float* __restrict__ x, fp16* __restrict__ w, int n)
{
    int i = (blockIdx.x * 256 + threadIdx.x) * 4;
    if (i + 3 >= n) {
        for (int j = i; j < n; j++) w[j] = __float2half_rn(x[j]);
        return;
    }
    float4 v = *(const float4*)(x + i);
    fp16 o0 = __float2half_rn(v.x), o1 = __float2half_rn(v.y);
    fp16 o2 = __float2half_rn(v.z), o3 = __float2half_rn(v.w);
    w[i]=o0; w[i+1]=o1; w[i+2]=o2; w[i+3]=o3;
}

// fold LoRA into weight, output fp16
__global__ void fold_f16_kernel(const float* __restrict__ W, const float* __restrict__ A,
                                const float* __restrict__ Bm, fp16* __restrict__ w,
                                int N, int K)
{
    int i = blockIdx.x * 256 + threadIdx.x;
    if (i >= N * K) return;
    int n = i / K;
    int k = i - n * K;
    float acc = W[i];
#pragma unroll
    for (int r = 0; r < 4; r++)
        acc += 0.25f * Bm[n * 4 + r] * A[r * K + k];
    w[i] = __float2half_rn(acc);
}

// ---------------------------------------------------------------------------
// Tensor-core GEMM: C[M,N] = A[M,K] @ W[N,K]^T (+bias)
// 2-pass fp16 split: C = Ah*W + Al*W.  BM=BN=128, BK=64, 2-stage cp.async,
// 256 threads (8 warps 4m x 2n, warp tile 32x64), 2 CTAs/SM.
// ---------------------------------------------------------------------------
#define SMSH   72                       // halves per smem row (64 + 8 pad)
#define PANELB (128 * SMSH * 2)         // 18432 B
#define STAGEB (3 * PANELB)             // A_hi, A_lo, B     = 55296 B
#define GDYN   (2 * STAGEB)             // 110592 B

__global__ void __launch_bounds__(256, 2) mma_gemm_kernel(
    const fp16* __restrict__ Ahi, const fp16* __restrict__ Alo,
    const fp16* __restrict__ Bw,
    const float* __restrict__ bias, float* __restrict__ C,
    int M, int N, int K)
{
    extern __shared__ fp16 smem_dyn[];
    const unsigned sbase = smem_u32(smem_dyn);

    const int tid  = threadIdx.x;
    const int warp = tid >> 5;
    const int lane = tid & 31;
    const int bm = blockIdx.y * 128;
    const int bn = blockIdx.x * 128;
    const int wm = (warp >> 1) * 32;
    const int wn = (warp & 1) * 64;

    // loader mapping: per panel 1024 chunks of 16B (row = c>>3, seg = c&7)
    unsigned dsta[4];
    int a_sz[4];
    size_t a_src[4], b_src[4];
#pragma unroll
    for (int j = 0; j < 4; j++) {
        int c   = tid + 256 * j;
        int row = c >> 3;
        int sl  = c & 7;
        dsta[j] = sbase + (unsigned)(row * SMSH + sl * 8) * 2;
        int gm = bm + row;
        a_sz[j]  = (gm < M) ? 16 : 0;
        int gm_c = (gm < M) ? gm : (M > 0 ? M - 1 : 0);
        a_src[j] = (size_t)gm_c * K + sl * 8;
        b_src[j] = (size_t)(bn + row) * K + sl * 8;
    }

    // ldmatrix base addresses (stage 0)
    unsigned a_addr[2], b_addr[4];
#pragma unroll
    for (int i = 0; i < 2; i++) {
        int row = wm + i * 16 + (lane & 15);
        int ko  = (lane >> 4) * 8;
        a_addr[i] = sbase + (unsigned)(row * SMSH + ko) * 2;
    }
#pragma unroll
    for (int jp = 0; jp < 4; jp++) {
        int grp = lane >> 3, lr = lane & 7;
        int row = wn + jp * 16 + ((grp >> 1) * 8) + lr;
        int ko  = (grp & 1) * 8;
        b_addr[jp] = sbase + 2u * PANELB + (unsigned)(row * SMSH + ko) * 2;
    }

    float acc[2][8][4];
#pragma unroll
    for (int i = 0; i < 2; i++)
#pragma unroll
        for (int j = 0; j < 8; j++)
#pragma unroll
            for (int r = 0; r < 4; r++) acc[i][j][r] = 0.f;

    const int KT = K >> 6;   // BK = 64

    auto load_stage = [&](int st, int kt) {
        const unsigned so = (unsigned)st * STAGEB;
        const int kb = kt * 64;
#pragma unroll
        for (int j = 0; j < 4; j++) {
            cpa16(dsta[j] + so,              Ahi + a_src[j] + kb, a_sz[j]);
            cpa16(dsta[j] + so + PANELB,     Alo + a_src[j] + kb, a_sz[j]);
            cpa16(dsta[j] + so + 2u*PANELB,  Bw  + b_src[j] + kb, 16);
        }
        asm volatile("cp.async.commit_group;\n");
    };

    load_stage(0, 0);

    for (int kt = 0; kt < KT; kt++) {
        asm volatile("cp.async.wait_group 0;\n" ::: "memory");
        __syncthreads();

        if (kt + 1 < KT) load_stage((kt + 1) & 1, kt + 1);

        const unsigned so = (unsigned)(kt & 1) * STAGEB;
#pragma unroll
        for (int ks = 0; ks < 4; ks++) {
            const unsigned kso = so + ks * 32;   // 16 halves = 32 B
            unsigned ah[2][4], al[2][4];
#pragma unroll
            for (int i = 0; i < 2; i++) {
                ldmx4(ah[i][0], ah[i][1], ah[i][2], ah[i][3], a_addr[i] + kso);
                ldmx4(al[i][0], al[i][1], al[i][2], al[i][3], a_addr[i] + kso + PANELB);
            }
#pragma unroll
            for (int jp = 0; jp < 4; jp++) {
                unsigned bw[2][2];
                ldmx4(bw[0][0], bw[0][1], bw[1][0], bw[1][1], b_addr[jp] + kso);
#pragma unroll
                for (int jj = 0; jj < 2; jj++) {
                    int j = jp * 2 + jj;
                    mma_f16(acc[0][j], ah[0], bw[jj]);
                    mma_f16(acc[1][j], ah[1], bw[jj]);
                }
#pragma unroll
                for (int jj = 0; jj < 2; jj++) {
                    int j = jp * 2 + jj;
                    mma_f16(acc[0][j], al[0], bw[jj]);
                    mma_f16(acc[1][j], al[1], bw[jj]);
                }
            }
        }
        __syncthreads();
    }

    // epilogue
#pragma unroll
    for (int i = 0; i < 2; i++) {
        int r0 = bm + wm + i * 16 + (lane >> 2);
#pragma unroll
        for (int j = 0; j < 8; j++) {
            int col = bn + wn + j * 8 + (lane & 3) * 2;
            float b0 = bias ? bias[col] : 0.f;
            float b1 = bias ? bias[col + 1] : 0.f;
            if (r0 < M) {
                float2 v = make_float2(acc[i][j][0] + b0, acc[i][j][1] + b1);
                *(float2*)(C + (size_t)r0 * N + col) = v;
            }
            if (r0 + 8 < M) {
                float2 v = make_float2(acc[i][j][2] + b0, acc[i][j][3] + b1);
                *(float2*)(C + (size_t)(r0 + 8) * N + col) = v;
            }
        }
    }
}

// ---------------------------------------------------------------------------
// Attention: one warp per query row, K/V staged in smem.
// ---------------------------------------------------------------------------
__global__ void __launch_bounds__(256) attn_kernel(
    const float* __restrict__ q, const float* __restrict__ k,
    const float* __restrict__ v, const int* __restrict__ toks,
    int Tkv, int maybe64, float* __restrict__ outF)
{
    extern __shared__ float sm[];
    float* Ks = sm;
    float* Vs = sm + Tkv * HD_;

    const int b  = blockIdx.z;
    const int h  = blockIdx.y;
    const int s0 = blockIdx.x * 64;
    const int tid = threadIdx.x;

    int is64 = 0;
    if (toks && maybe64)
        is64 = (toks[1] == 0 && toks[3] == 0 && toks[5] == 0 && toks[7] == 0);

    for (int i = tid; i < Tkv * HD_; i += 256) {
        int t = i / HD_;
        int d = i - t * HD_;
        int trow = t;
        if (toks) trow = is64 ? toks[2 * t] : toks[t];
        size_t gidx = ((size_t)b * T_ + trow) * D_ + h * HD_ + d;
        Ks[i] = k[gidx];
        Vs[i] = v[gidx];
    }
    __syncthreads();

    const int warp = tid >> 5;
    const int lane = tid & 31;
    const float scale = 0.07905694150420949f;
    const unsigned FULL = 0xffffffffu;

    for (int itq = 0; itq < 8; itq++) {
        int s = s0 + warp * 8 + itq;
        size_t base = ((size_t)b * S_ + s) * D_ + h * HD_;

        float qr[5];
#pragma unroll
        for (int j = 0; j < 5; j++) qr[j] = q[base + lane + 32 * j];

        float sc0 = 0.f, sc1 = 0.f, sc2 = 0.f;
        for (int t = 0; t < Tkv; t++) {
            float p = 0.f;
            const float* kr = Ks + t * HD_;
#pragma unroll
            for (int j = 0; j < 5; j++) p += qr[j] * kr[lane + 32 * j];
#pragma unroll
            for (int off = 16; off; off >>= 1)
                p += __shfl_xor_sync(FULL, p, off);
            float val = p * scale;
            if ((t & 31) == lane) {
                int slot = t >> 5;
                if      (slot == 0) sc0 = val;
                else if (slot == 1) sc1 = val;
                else                sc2 = val;
            }
        }

        float m = -1e30f;
        if (lane      < Tkv) m = fmaxf(m, sc0);
        if (32 + lane < Tkv) m = fmaxf(m, sc1);
        if (64 + lane < Tkv) m = fmaxf(m, sc2);
#pragma unroll
        for (int off = 16; off; off >>= 1)
            m = fmaxf(m, __shfl_xor_sync(FULL, m, off));

        float ssum;
        sc0 = (lane      < Tkv) ? expf(sc0 - m) : 0.f;
        sc1 = (32 + lane < Tkv) ? expf(sc1 - m) : 0.f;
        sc2 = (64 + lane < Tkv) ? expf(sc2 - m) : 0.f;
        ssum = sc0 + sc1 + sc2;
#pragma unroll
        for (int off = 16; off; off >>= 1)
            ssum += __shfl_xor_sync(FULL, ssum, off);
        float inv = 1.f / ssum;
        sc0 *= inv; sc1 *= inv; sc2 *= inv;

        float o[5] = {0.f, 0.f, 0.f, 0.f, 0.f};
        for (int t = 0; t < Tkv; t++) {
            float src = (t < 32) ? sc0 : ((t < 64) ? sc1 : sc2);
            float p = __shfl_sync(FULL, src, t & 31);
            const float* vr = Vs + t * HD_;
#pragma unroll
            for (int j = 0; j < 5; j++) o[j] += p * vr[lane + 32 * j];
        }
#pragma unroll
        for (int j = 0; j < 5; j++) outF[base + lane + 32 * j] = o[j];
    }
}

// ---------------------------------------------------------------------------
// Feature adapter
// ---------------------------------------------------------------------------
#define RPB 8
__global__ void __launch_bounds__(256) adapter_kernel(
    const float* __restrict__ x,
    const float* __restrict__ dW, const float* __restrict__ db,
    const float* __restrict__ uW, const float* __restrict__ ub,
    float* __restrict__ out)
{
    __shared__ float xs[RPB][D_];
    __shared__ float hb[RPB][RAD_];

    const size_t row0 = (size_t)blockIdx.x * RPB;
    const int tid = threadIdx.x;
    const unsigned FULL = 0xffffffffu;

    for (int i = tid; i < RPB * D_; i += 256) {
        int r = i / D_;
        int d = i - r * D_;
        xs[r][d] = x[(row0 + r) * D_ + d];
    }
    __syncthreads();

    const int warp = tid >> 5;
    const int lane = tid & 31;

    for (int j = warp; j < RAD_; j += 8) {
        const float* w = dW + (size_t)j * D_;
        float ps[RPB];
#pragma unroll
        for (int r = 0; r < RPB; r++) ps[r] = 0.f;
        for (int i = lane; i < D_; i += 32) {
            float wv = w[i];
#pragma unroll
            for (int r = 0; r < RPB; r++) ps[r] += xs[r][i] * wv;
        }
#pragma unroll
        for (int r = 0; r < RPB; r++) {
#pragma unroll
            for (int off = 16; off; off >>= 1)
                ps[r] += __shfl_xor_sync(FULL, ps[r], off);
        }
        if (lane == 0) {
            float dbj = db[j];
#pragma unroll
            for (int r = 0; r < RPB; r++) {
                float hv = ps[r] + dbj;
                hb[r][j] = 0.5f * hv * (1.f + erff(hv * 0.7071067811865475f));
            }
        }
    }
    __syncthreads();

    for (int d = tid; d < D_; d += 256) {
        float o[RPB];
        float ubd = ub[d];
#pragma unroll
        for (int r = 0; r < RPB; r++) o[r] = xs[r][d] + ubd;
        const float* uwp = uW + (size_t)d * RAD_;
#pragma unroll 16
        for (int j = 0; j < RAD_; j++) {
            float uv = uwp[j];
#pragma unroll
            for (int r = 0; r < RPB; r++) o[r] += hb[r][j] * uv;
        }
#pragma unroll
        for (int r = 0; r < RPB; r++) out[(row0 + r) * D_ + d] = o[r];
    }
}

// ---------------------------------------------------------------------------
// Launch
// ---------------------------------------------------------------------------
extern "C" void kernel_launch(void* const* d_in, const int* in_sizes, int n_in,
                              void* d_out, int out_size)
{
    const float* hs    = (const float*)d_in[0];
    const float* enc   = (const float*)d_in[1];
    const int*   e0    = (const int*)  d_in[2];
    const int*   e1    = (const int*)  d_in[3];
    const float* Wq    = (const float*)d_in[4];
    const float* Wk    = (const float*)d_in[5];
    const float* Wv    = (const float*)d_in[6];
    const float* Wo    = (const float*)d_in[7];
    const float* bo    = (const float*)d_in[8];
    const float* lkA   = (const float*)d_in[9];
    const float* lkB   = (const float*)d_in[10];
    const float* lvA   = (const float*)d_in[11];
    const float* lvB   = (const float*)d_in[12];
    const float* loA   = (const float*)d_in[13];
    const float* loB   = (const float*)d_in[14];
    const float* a0dW  = (const float*)d_in[15];
    const float* a0db  = (const float*)d_in[16];
    const float* a0uW  = (const float*)d_in[17];
    const float* a0ub  = (const float*)d_in[18];
    const float* a1dW  = (const float*)d_in[19];
    const float* a1db  = (const float*)d_in[20];
    const float* a1uW  = (const float*)d_in[21];
    const float* a1ub  = (const float*)d_in[22];

    float *qp, *fgp, *f0p, *f1p, *kp, *vp;
    fp16 *hsh, *hsl, *fgh, *fgl, *ench, *encl, *wq, *wo, *wk, *wv;
    cudaGetSymbolAddress((void**)&qp,   g_q);
    cudaGetSymbolAddress((void**)&fgp,  g_Fg);
    cudaGetSymbolAddress((void**)&f0p,  g_F0);
    cudaGetSymbolAddress((void**)&f1p,  g_F1);
    cudaGetSymbolAddress((void**)&kp,   g_k);
    cudaGetSymbolAddress((void**)&vp,   g_v);
    cudaGetSymbolAddress((void**)&hsh,  g_hs_hi);
    cudaGetSymbolAddress((void**)&hsl,  g_hs_lo);
    cudaGetSymbolAddress((void**)&fgh,  g_fg_hi);
    cudaGetSymbolAddress((void**)&fgl,  g_fg_lo);
    cudaGetSymbolAddress((void**)&ench, g_enc_hi);
    cudaGetSymbolAddress((void**)&encl, g_enc_lo);
    cudaGetSymbolAddress((void**)&wq,   g_wq);
    cudaGetSymbolAddress((void**)&wo,   g_wo);
    cudaGetSymbolAddress((void**)&wk,   g_wk);
    cudaGetSymbolAddress((void**)&wv,   g_wv);

    float* out = (float*)d_out;

    cudaFuncSetAttribute(mma_gemm_kernel,
                         cudaFuncAttributeMaxDynamicSharedMemorySize, GDYN);
    cudaFuncSetAttribute(attn_kernel,
                         cudaFuncAttributeMaxDynamicSharedMemorySize, 101376);

    // 1-4: conversions + Wk fold
    convert2_kernel<<<(M_BS * D_ / 4 + 255) / 256, 256>>>(hs,  hsh,  hsl,  M_BS * D_);
    convertw_kernel<<<(D_ * D_ / 4 + 255) / 256, 256>>>(Wq, wq, D_ * D_);
    convert2_kernel<<<(M_BT * DT_ / 4 + 255) / 256, 256>>>(enc, ench, encl, M_BT * DT_);
    fold_f16_kernel<<<(D_ * DT_ + 255) / 256, 256>>>(Wk, lkA, lkB, wk, D_, DT_);

    // 5: q projection, 6: k projection  (ncu capture window)
    dim3 gq(D_ / 128, M_BS / 128);
    mma_gemm_kernel<<<gq, 256, GDYN>>>(hsh, hsl, wq, nullptr, qp, M_BS, D_, D_);
    dim3 gkv(D_ / 128, (M_BT + 127) / 128);
    mma_gemm_kernel<<<gkv, 256, GDYN>>>(ench, encl, wk, nullptr, kp, M_BT, D_, DT_);

    // 7-9: fold Wv, v projection, fold Wo
    fold_f16_kernel<<<(D_ * DT_ + 255) / 256, 256>>>(Wv, lvA, lvB, wv, D_, DT_);
    mma_gemm_kernel<<<gkv, 256, GDYN>>>(ench, encl, wv, nullptr, vp, M_BT, D_, DT_);
    fold_f16_kernel<<<(D_ * D_  + 255) / 256, 256>>>(Wo, loA, loB, wo, D_, D_);

    // attention
    dim3 ga(S_ / 64, H_, B_);
    attn_kernel<<<ga, 256, (size_t)T_ * HD_ * 2 * sizeof(float)>>>(
        qp, kp, vp, nullptr, T_, 0, fgp);
    attn_kernel<<<ga, 256, (size_t)8 * HD_ * 2 * sizeof(float)>>>(
        qp, kp, vp, e0, 8, 1, f0p);
    attn_kernel<<<ga, 256, (size_t)12 * HD_ * 2 * sizeof(float)>>>(
        qp, kp, vp, e1, 12, 0, f1p);

    // adapters
    adapter_kernel<<<M_BS / RPB, 256>>>(f0p, a0dW, a0db, a0uW, a0ub, out + OFF_);
    adapter_kernel<<<M_BS / RPB, 256>>>(f1p, a1dW, a1db, a1uW, a1ub, out + 2 * OFF_);

    // F_g convert + output projection
    convert2_kernel<<<(M_BS * D_ / 4 + 255) / 256, 256>>>(fgp, fgh, fgl, M_BS * D_);
    mma_gemm_kernel<<<gq, 256, GDYN>>>(fgh, fgl, wo, bo, out, M_BS, D_, D_);
}

// round 8
// speedup vs baseline: 1.9381x; 1.0479x over previous
#include <cuda_runtime.h>
#include <cuda_fp16.h>
#include <math.h>
#include <stdint.h>
#include <stddef.h>

// ---------------------------------------------------------------------------
// Problem constants
// ---------------------------------------------------------------------------
#define B_   4
#define S_   4096
#define T_   77
#define D_   1280
#define DT_  768
#define H_   8
#define HD_  160
#define RAD_ 64
#define M_BS (B_*S_)   // 16384
#define M_BT (B_*T_)   // 308
#define OFF_ ((size_t)M_BS * D_)

typedef __half fp16;

// ---------------------------------------------------------------------------
// Device scratch
// ---------------------------------------------------------------------------
__device__ float g_q  [M_BS * D_];
__device__ float g_F0 [M_BS * D_];
__device__ float g_F1 [M_BS * D_];
__device__ float g_k  [M_BT * D_];
__device__ float g_v  [M_BT * D_];

__device__ fp16 g_hs_hi [M_BS * D_];
__device__ fp16 g_hs_lo [M_BS * D_];
__device__ fp16 g_fg_hi [M_BS * D_];
__device__ fp16 g_fg_lo [M_BS * D_];
__device__ fp16 g_enc_hi[M_BT * DT_];
__device__ fp16 g_enc_lo[M_BT * DT_];
__device__ fp16 g_wq [D_ * D_];
__device__ fp16 g_wo [D_ * D_];
__device__ fp16 g_wk [D_ * DT_];
__device__ fp16 g_wv [D_ * DT_];

// ---------------------------------------------------------------------------
// helpers
// ---------------------------------------------------------------------------
__device__ __forceinline__ unsigned smem_u32(const void* p) {
    return (unsigned)__cvta_generic_to_shared(p);
}
__device__ __forceinline__ void cpa16(unsigned dst, const fp16* src, int sz) {
    asm volatile("cp.async.cg.shared.global [%0], [%1], 16, %2;\n"
                 :: "r"(dst), "l"(src), "r"(sz));
}
__device__ __forceinline__ void ldmx4(unsigned& r0, unsigned& r1, unsigned& r2, unsigned& r3, unsigned addr) {
    asm volatile("ldmatrix.sync.aligned.m8n8.x4.shared.b16 {%0,%1,%2,%3}, [%4];"
                 : "=r"(r0), "=r"(r1), "=r"(r2), "=r"(r3) : "r"(addr));
}
__device__ __forceinline__ void mma_f16(float* d, const unsigned* a, const unsigned* b) {
    asm volatile(
        "mma.sync.aligned.m16n8k16.row.col.f32.f16.f16.f32 "
        "{%0,%1,%2,%3}, {%4,%5,%6,%7}, {%8,%9}, {%0,%1,%2,%3};"
        : "+f"(d[0]), "+f"(d[1]), "+f"(d[2]), "+f"(d[3])
        : "r"(a[0]), "r"(a[1]), "r"(a[2]), "r"(a[3]), "r"(b[0]), "r"(b[1]));
}

__device__ __forceinline__ void split_f16(float x, fp16& hi, fp16& lo) {
    hi = __float2half_rn(x);
    lo = __float2half_rn(x - __half2float(hi));
}

// fp32 -> fp16 hi/lo (activations)
__global__ void convert2_kernel(const float* __restrict__ x,
                                fp16* __restrict__ hi, fp16* __restrict__ lo, int n)
{
    int i = (blockIdx.x * 256 + threadIdx.x) * 4;
    if (i + 3 >= n) {
        for (int j = i; j < n; j++) { fp16 h, l; split_f16(x[j], h, l); hi[j] = h; lo[j] = l; }
        return;
    }
    float4 v = *(const float4*)(x + i);
    fp16 h0,l0,h1,l1,h2,l2,h3,l3;
    split_f16(v.x,h0,l0); split_f16(v.y,h1,l1); split_f16(v.z,h2,l2); split_f16(v.w,h3,l3);
    hi[i]=h0; hi[i+1]=h1; hi[i+2]=h2; hi[i+3]=h3;
    lo[i]=l0; lo[i+1]=l1; lo[i+2]=l2; lo[i+3]=l3;
}

// fp32 -> fp16 single (weights)
__global__ void convertw_kernel(const float* __restrict__ x, fp16* __restrict__ w, int n)
{
    int i = (blockIdx.x * 256 + threadIdx.x) * 4;
    if (i + 3 >= n) {
        for (int j = i; j < n; j++) w[j] = __float2half_rn(x[j]);
        return;
    }
    float4 v = *(const float4*)(x + i);
    fp16 o0 = __float2half_rn(v.x), o1 = __float2half_rn(v.y);
    fp16 o2 = __float2half_rn(v.z), o3 = __float2half_rn(v.w);
    w[i]=o0; w[i+1]=o1; w[i+2]=o2; w[i+3]=o3;
}

// fold LoRA into weight, output fp16
__global__ void fold_f16_kernel(const float* __restrict__ W, const float* __restrict__ A,
                                const float* __restrict__ Bm, fp16* __restrict__ w,
                                int N, int K)
{
    int i = blockIdx.x * 256 + threadIdx.x;
    if (i >= N * K) return;
    int n = i / K;
    int k = i - n * K;
    float acc = W[i];
#pragma unroll
    for (int r = 0; r < 4; r++)
        acc += 0.25f * Bm[n * 4 + r] * A[r * K + k];
    w[i] = __float2half_rn(acc);
}

// ---------------------------------------------------------------------------
// Tensor-core GEMM: C[M,N] = A[M,K] @ W[N,K]^T (+bias)
// 2-pass fp16 split: C = Ah*W + Al*W.  BM=BN=128, BK=64, 2-stage cp.async,
// 256 threads (8 warps 4m x 2n, warp tile 32x64), 2 CTAs/SM.
// Optional second problem via blockIdx.z (Bw2/C2) sharing the same A.
// ---------------------------------------------------------------------------
#define SMSH   72                       // halves per smem row (64 + 8 pad)
#define PANELB (128 * SMSH * 2)         // 18432 B
#define STAGEB (3 * PANELB)             // A_hi, A_lo, B     = 55296 B
#define GDYN   (2 * STAGEB)             // 110592 B

__global__ void __launch_bounds__(256, 2) mma_gemm_kernel(
    const fp16* __restrict__ Ahi, const fp16* __restrict__ Alo,
    const fp16* __restrict__ Bw,  const fp16* __restrict__ Bw2,
    const float* __restrict__ bias, float* __restrict__ C, float* __restrict__ C2,
    int M, int N, int K)
{
    extern __shared__ fp16 smem_dyn[];
    const unsigned sbase = smem_u32(smem_dyn);

    const fp16* Bsel = (blockIdx.z == 0) ? Bw : Bw2;
    float*      Csel = (blockIdx.z == 0) ? C  : C2;

    const int tid  = threadIdx.x;
    const int warp = tid >> 5;
    const int lane = tid & 31;
    const int bm = blockIdx.y * 128;
    const int bn = blockIdx.x * 128;
    const int wm = (warp >> 1) * 32;
    const int wn = (warp & 1) * 64;

    // loader mapping: per panel 1024 chunks of 16B (row = c>>3, seg = c&7)
    unsigned dsta[4];
    int a_sz[4];
    size_t a_src[4], b_src[4];
#pragma unroll
    for (int j = 0; j < 4; j++) {
        int c   = tid + 256 * j;
        int row = c >> 3;
        int sl  = c & 7;
        dsta[j] = sbase + (unsigned)(row * SMSH + sl * 8) * 2;
        int gm = bm + row;
        a_sz[j]  = (gm < M) ? 16 : 0;
        int gm_c = (gm < M) ? gm : (M > 0 ? M - 1 : 0);
        a_src[j] = (size_t)gm_c * K + sl * 8;
        b_src[j] = (size_t)(bn + row) * K + sl * 8;
    }

    // ldmatrix base addresses (stage 0)
    unsigned a_addr[2], b_addr[4];
#pragma unroll
    for (int i = 0; i < 2; i++) {
        int row = wm + i * 16 + (lane & 15);
        int ko  = (lane >> 4) * 8;
        a_addr[i] = sbase + (unsigned)(row * SMSH + ko) * 2;
    }
#pragma unroll
    for (int jp = 0; jp < 4; jp++) {
        int grp = lane >> 3, lr = lane & 7;
        int row = wn + jp * 16 + ((grp >> 1) * 8) + lr;
        int ko  = (grp & 1) * 8;
        b_addr[jp] = sbase + 2u * PANELB + (unsigned)(row * SMSH + ko) * 2;
    }

    float acc[2][8][4];
#pragma unroll
    for (int i = 0; i < 2; i++)
#pragma unroll
        for (int j = 0; j < 8; j++)
#pragma unroll
            for (int r = 0; r < 4; r++) acc[i][j][r] = 0.f;

    const int KT = K >> 6;   // BK = 64

    auto load_stage = [&](int st, int kt) {
        const unsigned so = (unsigned)st * STAGEB;
        const int kb = kt * 64;
#pragma unroll
        for (int j = 0; j < 4; j++) {
            cpa16(dsta[j] + so,              Ahi  + a_src[j] + kb, a_sz[j]);
            cpa16(dsta[j] + so + PANELB,     Alo  + a_src[j] + kb, a_sz[j]);
            cpa16(dsta[j] + so + 2u*PANELB,  Bsel + b_src[j] + kb, 16);
        }
        asm volatile("cp.async.commit_group;\n");
    };

    load_stage(0, 0);

    for (int kt = 0; kt < KT; kt++) {
        asm volatile("cp.async.wait_group 0;\n" ::: "memory");
        __syncthreads();

        if (kt + 1 < KT) load_stage((kt + 1) & 1, kt + 1);

        const unsigned so = (unsigned)(kt & 1) * STAGEB;
#pragma unroll
        for (int ks = 0; ks < 4; ks++) {
            const unsigned kso = so + ks * 32;   // 16 halves = 32 B
            unsigned ah[2][4], al[2][4];
#pragma unroll
            for (int i = 0; i < 2; i++) {
                ldmx4(ah[i][0], ah[i][1], ah[i][2], ah[i][3], a_addr[i] + kso);
                ldmx4(al[i][0], al[i][1], al[i][2], al[i][3], a_addr[i] + kso + PANELB);
            }
#pragma unroll
            for (int jp = 0; jp < 4; jp++) {
                unsigned bw[2][2];
                ldmx4(bw[0][0], bw[0][1], bw[1][0], bw[1][1], b_addr[jp] + kso);
#pragma unroll
                for (int jj = 0; jj < 2; jj++) {
                    int j = jp * 2 + jj;
                    mma_f16(acc[0][j], ah[0], bw[jj]);
                    mma_f16(acc[1][j], ah[1], bw[jj]);
                }
#pragma unroll
                for (int jj = 0; jj < 2; jj++) {
                    int j = jp * 2 + jj;
                    mma_f16(acc[0][j], al[0], bw[jj]);
                    mma_f16(acc[1][j], al[1], bw[jj]);
                }
            }
        }
        __syncthreads();
    }

    // epilogue
#pragma unroll
    for (int i = 0; i < 2; i++) {
        int r0 = bm + wm + i * 16 + (lane >> 2);
#pragma unroll
        for (int j = 0; j < 8; j++) {
            int col = bn + wn + j * 8 + (lane & 3) * 2;
            float b0 = bias ? bias[col] : 0.f;
            float b1 = bias ? bias[col + 1] : 0.f;
            if (r0 < M) {
                float2 v = make_float2(acc[i][j][0] + b0, acc[i][j][1] + b1);
                *(float2*)(Csel + (size_t)r0 * N + col) = v;
            }
            if (r0 + 8 < M) {
                float2 v = make_float2(acc[i][j][2] + b0, acc[i][j][3] + b1);
                *(float2*)(Csel + (size_t)(r0 + 8) * N + col) = v;
            }
        }
    }
}

// ---------------------------------------------------------------------------
// Attention, templated on TKV for full unroll / ILP across shfl chains.
// WSPLIT=1: write fp16 hi/lo (feeds out-proj GEMM); else fp32.
// ---------------------------------------------------------------------------
template<int TKV, int WSPLIT>
__global__ void __launch_bounds__(256) attn_kernel_t(
    const float* __restrict__ q, const float* __restrict__ k,
    const float* __restrict__ v, const int* __restrict__ toks,
    int maybe64, float* __restrict__ outF,
    fp16* __restrict__ outH, fp16* __restrict__ outL)
{
    constexpr int NS = (TKV + 31) / 32;
    extern __shared__ float sm[];
    float* Ks = sm;
    float* Vs = sm + TKV * HD_;

    const int b  = blockIdx.z;
    const int h  = blockIdx.y;
    const int s0 = blockIdx.x * 64;
    const int tid = threadIdx.x;

    int is64 = 0;
    if (toks && maybe64)
        is64 = (toks[1] == 0 && toks[3] == 0 && toks[5] == 0 && toks[7] == 0);

    if (toks) {
        for (int i = tid; i < TKV * HD_; i += 256) {
            int t = i / HD_;
            int d = i - t * HD_;
            int trow = is64 ? toks[2 * t] : toks[t];
            size_t gidx = ((size_t)b * T_ + trow) * D_ + h * HD_ + d;
            Ks[i] = k[gidx];
            Vs[i] = v[gidx];
        }
    } else {
        // contiguous rows: vectorized copy (TKV*HD_ % 4 == 0)
        const float* kb = k + (size_t)b * T_ * D_ + h * HD_;
        const float* vb = v + (size_t)b * T_ * D_ + h * HD_;
        for (int i = tid * 4; i < TKV * HD_; i += 1024) {
            int t = i / HD_;
            int d = i - t * HD_;
            // HD_=160 divisible by 4, rows remain 4-aligned
            *(float4*)(Ks + i) = *(const float4*)(kb + (size_t)t * D_ + d);
            *(float4*)(Vs + i) = *(const float4*)(vb + (size_t)t * D_ + d);
        }
    }
    __syncthreads();

    const int warp = tid >> 5;
    const int lane = tid & 31;
    const float scale = 0.07905694150420949f;
    const unsigned FULL = 0xffffffffu;

    for (int itq = 0; itq < 8; itq++) {
        int s = s0 + warp * 8 + itq;
        size_t base = ((size_t)b * S_ + s) * D_ + h * HD_;

        float qr[5];
#pragma unroll
        for (int j = 0; j < 5; j++) qr[j] = q[base + lane + 32 * j];

        float sc[NS];
#pragma unroll
        for (int n = 0; n < NS; n++) sc[n] = 0.f;

#pragma unroll 4
        for (int t = 0; t < TKV; t++) {
            float p = 0.f;
            const float* kr = Ks + t * HD_;
#pragma unroll
            for (int j = 0; j < 5; j++) p += qr[j] * kr[lane + 32 * j];
#pragma unroll
            for (int off = 16; off; off >>= 1)
                p += __shfl_xor_sync(FULL, p, off);
            if ((t & 31) == lane) sc[t >> 5] = p * scale;
        }

        float m = -1e30f;
#pragma unroll
        for (int n = 0; n < NS; n++)
            if (n * 32 + lane < TKV) m = fmaxf(m, sc[n]);
#pragma unroll
        for (int off = 16; off; off >>= 1)
            m = fmaxf(m, __shfl_xor_sync(FULL, m, off));

        float ssum = 0.f;
#pragma unroll
        for (int n = 0; n < NS; n++) {
            sc[n] = (n * 32 + lane < TKV) ? expf(sc[n] - m) : 0.f;
            ssum += sc[n];
        }
#pragma unroll
        for (int off = 16; off; off >>= 1)
            ssum += __shfl_xor_sync(FULL, ssum, off);
        float inv = 1.f / ssum;
#pragma unroll
        for (int n = 0; n < NS; n++) sc[n] *= inv;

        float o[5] = {0.f, 0.f, 0.f, 0.f, 0.f};
#pragma unroll 4
        for (int t = 0; t < TKV; t++) {
            float p = __shfl_sync(FULL, sc[t >> 5], t & 31);
            const float* vr = Vs + t * HD_;
#pragma unroll
            for (int j = 0; j < 5; j++) o[j] += p * vr[lane + 32 * j];
        }

        if (WSPLIT) {
#pragma unroll
            for (int j = 0; j < 5; j++) {
                fp16 hh, ll; split_f16(o[j], hh, ll);
                outH[base + lane + 32 * j] = hh;
                outL[base + lane + 32 * j] = ll;
            }
        } else {
#pragma unroll
            for (int j = 0; j < 5; j++) outF[base + lane + 32 * j] = o[j];
        }
    }
}

// ---------------------------------------------------------------------------
// Feature adapter
// ---------------------------------------------------------------------------
#define RPB 8
__global__ void __launch_bounds__(256) adapter_kernel(
    const float* __restrict__ x,
    const float* __restrict__ dW, const float* __restrict__ db,
    const float* __restrict__ uW, const float* __restrict__ ub,
    float* __restrict__ out)
{
    __shared__ float xs[RPB][D_];
    __shared__ float hb[RPB][RAD_];

    const size_t row0 = (size_t)blockIdx.x * RPB;
    const int tid = threadIdx.x;
    const unsigned FULL = 0xffffffffu;

    for (int i = tid; i < RPB * D_; i += 256) {
        int r = i / D_;
        int d = i - r * D_;
        xs[r][d] = x[(row0 + r) * D_ + d];
    }
    __syncthreads();

    const int warp = tid >> 5;
    const int lane = tid & 31;

    for (int j = warp; j < RAD_; j += 8) {
        const float* w = dW + (size_t)j * D_;
        float ps[RPB];
#pragma unroll
        for (int r = 0; r < RPB; r++) ps[r] = 0.f;
        for (int i = lane; i < D_; i += 32) {
            float wv = w[i];
#pragma unroll
            for (int r = 0; r < RPB; r++) ps[r] += xs[r][i] * wv;
        }
#pragma unroll
        for (int r = 0; r < RPB; r++) {
#pragma unroll
            for (int off = 16; off; off >>= 1)
                ps[r] += __shfl_xor_sync(FULL, ps[r], off);
        }
        if (lane == 0) {
            float dbj = db[j];
#pragma unroll
            for (int r = 0; r < RPB; r++) {
                float hv = ps[r] + dbj;
                hb[r][j] = 0.5f * hv * (1.f + erff(hv * 0.7071067811865475f));
            }
        }
    }
    __syncthreads();

    for (int d = tid; d < D_; d += 256) {
        float o[RPB];
        float ubd = ub[d];
#pragma unroll
        for (int r = 0; r < RPB; r++) o[r] = xs[r][d] + ubd;
        const float* uwp = uW + (size_t)d * RAD_;
#pragma unroll 16
        for (int j = 0; j < RAD_; j++) {
            float uv = uwp[j];
#pragma unroll
            for (int r = 0; r < RPB; r++) o[r] += hb[r][j] * uv;
        }
#pragma unroll
        for (int r = 0; r < RPB; r++) out[(row0 + r) * D_ + d] = o[r];
    }
}

// ---------------------------------------------------------------------------
// Launch
// ---------------------------------------------------------------------------
extern "C" void kernel_launch(void* const* d_in, const int* in_sizes, int n_in,
                              void* d_out, int out_size)
{
    const float* hs    = (const float*)d_in[0];
    const float* enc   = (const float*)d_in[1];
    const int*   e0    = (const int*)  d_in[2];
    const int*   e1    = (const int*)  d_in[3];
    const float* Wq    = (const float*)d_in[4];
    const float* Wk    = (const float*)d_in[5];
    const float* Wv    = (const float*)d_in[6];
    const float* Wo    = (const float*)d_in[7];
    const float* bo    = (const float*)d_in[8];
    const float* lkA   = (const float*)d_in[9];
    const float* lkB   = (const float*)d_in[10];
    const float* lvA   = (const float*)d_in[11];
    const float* lvB   = (const float*)d_in[12];
    const float* loA   = (const float*)d_in[13];
    const float* loB   = (const float*)d_in[14];
    const float* a0dW  = (const float*)d_in[15];
    const float* a0db  = (const float*)d_in[16];
    const float* a0uW  = (const float*)d_in[17];
    const float* a0ub  = (const float*)d_in[18];
    const float* a1dW  = (const float*)d_in[19];
    const float* a1db  = (const float*)d_in[20];
    const float* a1uW  = (const float*)d_in[21];
    const float* a1ub  = (const float*)d_in[22];

    float *qp, *f0p, *f1p, *kp, *vp;
    fp16 *hsh, *hsl, *fgh, *fgl, *ench, *encl, *wq, *wo, *wk, *wv;
    cudaGetSymbolAddress((void**)&qp,   g_q);
    cudaGetSymbolAddress((void**)&f0p,  g_F0);
    cudaGetSymbolAddress((void**)&f1p,  g_F1);
    cudaGetSymbolAddress((void**)&kp,   g_k);
    cudaGetSymbolAddress((void**)&vp,   g_v);
    cudaGetSymbolAddress((void**)&hsh,  g_hs_hi);
    cudaGetSymbolAddress((void**)&hsl,  g_hs_lo);
    cudaGetSymbolAddress((void**)&fgh,  g_fg_hi);
    cudaGetSymbolAddress((void**)&fgl,  g_fg_lo);
    cudaGetSymbolAddress((void**)&ench, g_enc_hi);
    cudaGetSymbolAddress((void**)&encl, g_enc_lo);
    cudaGetSymbolAddress((void**)&wq,   g_wq);
    cudaGetSymbolAddress((void**)&wo,   g_wo);
    cudaGetSymbolAddress((void**)&wk,   g_wk);
    cudaGetSymbolAddress((void**)&wv,   g_wv);

    float* out = (float*)d_out;

    cudaFuncSetAttribute(mma_gemm_kernel,
                         cudaFuncAttributeMaxDynamicSharedMemorySize, GDYN);
    cudaFuncSetAttribute(attn_kernel_t<77,1>,
                         cudaFuncAttributeMaxDynamicSharedMemorySize, 101376);

    // 1-3: conversions feeding q-GEMM
    convert2_kernel<<<(M_BS * D_ / 4 + 255) / 256, 256>>>(hs,  hsh,  hsl,  M_BS * D_);
    convertw_kernel<<<(D_ * D_ / 4 + 255) / 256, 256>>>(Wq, wq, D_ * D_);
    convert2_kernel<<<(M_BT * DT_ / 4 + 255) / 256, 256>>>(enc, ench, encl, M_BT * DT_);

    // 4: q projection  <-- ncu capture slot
    dim3 gq(D_ / 128, M_BS / 128, 1);
    mma_gemm_kernel<<<gq, 256, GDYN>>>(hsh, hsl, wq, nullptr, nullptr,
                                       qp, nullptr, M_BS, D_, D_);

    // 5-7: weight folds
    fold_f16_kernel<<<(D_ * DT_ + 255) / 256, 256>>>(Wk, lkA, lkB, wk, D_, DT_);
    fold_f16_kernel<<<(D_ * DT_ + 255) / 256, 256>>>(Wv, lvA, lvB, wv, D_, DT_);
    fold_f16_kernel<<<(D_ * D_  + 255) / 256, 256>>>(Wo, loA, loB, wo, D_, D_);

    // 8: merged k+v projections (blockIdx.z selects weight/output)
    dim3 gkv(D_ / 128, (M_BT + 127) / 128, 2);
    mma_gemm_kernel<<<gkv, 256, GDYN>>>(ench, encl, wk, wv, nullptr,
                                        kp, vp, M_BT, D_, DT_);

    // 9-11: attention (global writes fp16 hi/lo directly for out-proj)
    dim3 ga(S_ / 64, H_, B_);
    attn_kernel_t<77,1><<<ga, 256, (size_t)T_ * HD_ * 2 * sizeof(float)>>>(
        qp, kp, vp, nullptr, 0, nullptr, fgh, fgl);
    attn_kernel_t<8,0><<<ga, 256, (size_t)8 * HD_ * 2 * sizeof(float)>>>(
        qp, kp, vp, e0, 1, f0p, nullptr, nullptr);
    attn_kernel_t<12,0><<<ga, 256, (size_t)12 * HD_ * 2 * sizeof(float)>>>(
        qp, kp, vp, e1, 0, f1p, nullptr, nullptr);

    // 12-13: adapters
    adapter_kernel<<<M_BS / RPB, 256>>>(f0p, a0dW, a0db, a0uW, a0ub, out + OFF_);
    adapter_kernel<<<M_BS / RPB, 256>>>(f1p, a1dW, a1db, a1uW, a1ub, out + 2 * OFF_);

    // 14: output projection
    mma_gemm_kernel<<<gq, 256, GDYN>>>(fgh, fgl, wo, nullptr, bo,
                                       out, nullptr, M_BS, D_, D_);
}

// round 10
// speedup vs baseline: 4.0432x; 2.0862x over previous
#include <cuda_runtime.h>
#include <cuda_fp16.h>
#include <math.h>
#include <stdint.h>
#include <stddef.h>

// ---------------------------------------------------------------------------
// Problem constants
// ---------------------------------------------------------------------------
#define B_   4
#define S_   4096
#define T_   77
#define D_   1280
#define DT_  768
#define H_   8
#define HD_  160
#define RAD_ 64
#define M_BS (B_*S_)   // 16384
#define M_BT (B_*T_)   // 308
#define OFF_ ((size_t)M_BS * D_)

typedef __half fp16;

// ---------------------------------------------------------------------------
// Device scratch
// ---------------------------------------------------------------------------
__device__ float g_q  [M_BS * D_];
__device__ float g_k  [M_BT * D_];
__device__ float g_v  [M_BT * D_];

__device__ fp16 g_hs_hi [M_BS * D_];
__device__ fp16 g_hs_lo [M_BS * D_];
__device__ fp16 g_fg_hi [M_BS * D_];
__device__ fp16 g_fg_lo [M_BS * D_];
__device__ fp16 g_f0_hi [M_BS * D_];
__device__ fp16 g_f0_lo [M_BS * D_];
__device__ fp16 g_f1_hi [M_BS * D_];
__device__ fp16 g_f1_lo [M_BS * D_];
__device__ fp16 g_enc_hi[M_BT * DT_];
__device__ fp16 g_enc_lo[M_BT * DT_];
__device__ fp16 g_wq [D_ * D_];
__device__ fp16 g_wo [D_ * D_];
__device__ fp16 g_wk [D_ * DT_];
__device__ fp16 g_wv [D_ * DT_];
__device__ fp16 g_dw0[RAD_ * D_];
__device__ fp16 g_dw1[RAD_ * D_];
__device__ fp16 g_uw0[D_ * RAD_];
__device__ fp16 g_uw1[D_ * RAD_];
__device__ fp16 g_H  [2 * M_BS * RAD_];

// ---------------------------------------------------------------------------
// helpers
// ---------------------------------------------------------------------------
__device__ __forceinline__ unsigned smem_u32(const void* p) {
    return (unsigned)__cvta_generic_to_shared(p);
}
__device__ __forceinline__ void cpa16(unsigned dst, const fp16* src, int sz) {
    asm volatile("cp.async.cg.shared.global [%0], [%1], 16, %2;\n"
                 :: "r"(dst), "l"(src), "r"(sz));
}
__device__ __forceinline__ void ldmx4(unsigned& r0, unsigned& r1, unsigned& r2, unsigned& r3, unsigned addr) {
    asm volatile("ldmatrix.sync.aligned.m8n8.x4.shared.b16 {%0,%1,%2,%3}, [%4];"
                 : "=r"(r0), "=r"(r1), "=r"(r2), "=r"(r3) : "r"(addr));
}
__device__ __forceinline__ void mma_f16(float* d, const unsigned* a, const unsigned* b) {
    asm volatile(
        "mma.sync.aligned.m16n8k16.row.col.f32.f16.f16.f32 "
        "{%0,%1,%2,%3}, {%4,%5,%6,%7}, {%8,%9}, {%0,%1,%2,%3};"
        : "+f"(d[0]), "+f"(d[1]), "+f"(d[2]), "+f"(d[3])
        : "r"(a[0]), "r"(a[1]), "r"(a[2]), "r"(a[3]), "r"(b[0]), "r"(b[1]));
}
__device__ __forceinline__ void split_f16(float x, fp16& hi, fp16& lo) {
    hi = __float2half_rn(x);
    lo = __float2half_rn(x - __half2float(hi));
}
__device__ __forceinline__ float gelu_exact(float x) {
    return 0.5f * x * (1.f + erff(x * 0.7071067811865475f));
}

// ---------------------------------------------------------------------------
// prep: all converts + LoRA folds fused (region-dispatched)
// ---------------------------------------------------------------------------
#define HS_C   5242880L   // M_BS*D_/4
#define ENC_C  59136L     // M_BT*DT_/4
#define WQ_C   409600L    // D_*D_/4
#define AD_C   20480L     // RAD_*D_/4 (per array)
#define WK_N   983040L    // D_*DT_
#define WO_N   1638400L   // D_*D_
#define PREP_TOT (HS_C + ENC_C + WQ_C + 4*AD_C + 2*WK_N + WO_N)

__device__ __forceinline__ void cvt2_v4(const float* x, fp16* hi, fp16* lo, long i) {
    float4 v = *(const float4*)(x + i);
    fp16 h0,l0,h1,l1,h2,l2,h3,l3;
    split_f16(v.x,h0,l0); split_f16(v.y,h1,l1); split_f16(v.z,h2,l2); split_f16(v.w,h3,l3);
    hi[i]=h0; hi[i+1]=h1; hi[i+2]=h2; hi[i+3]=h3;
    lo[i]=l0; lo[i+1]=l1; lo[i+2]=l2; lo[i+3]=l3;
}
__device__ __forceinline__ void cvt1_v4(const float* x, fp16* w, long i) {
    float4 v = *(const float4*)(x + i);
    w[i]   = __float2half_rn(v.x); w[i+1] = __float2half_rn(v.y);
    w[i+2] = __float2half_rn(v.z); w[i+3] = __float2half_rn(v.w);
}
__device__ __forceinline__ void fold1(const float* W, const float* A, const float* Bm,
                                      fp16* w, int K, long i) {
    int n = (int)(i / K);
    int k = (int)(i - (long)n * K);
    float acc = W[i];
#pragma unroll
    for (int r = 0; r < 4; r++)
        acc += 0.25f * Bm[n * 4 + r] * A[r * K + k];
    w[i] = __float2half_rn(acc);
}

__global__ void prep_kernel(
    const float* __restrict__ hs, const float* __restrict__ enc, const float* __restrict__ Wq,
    const float* __restrict__ a0dW, const float* __restrict__ a1dW,
    const float* __restrict__ a0uW, const float* __restrict__ a1uW,
    const float* __restrict__ Wk, const float* __restrict__ lkA, const float* __restrict__ lkB,
    const float* __restrict__ Wv, const float* __restrict__ lvA, const float* __restrict__ lvB,
    const float* __restrict__ Wo, const float* __restrict__ loA, const float* __restrict__ loB,
    fp16* hsh, fp16* hsl, fp16* ench, fp16* encl, fp16* wq,
    fp16* dw0, fp16* dw1, fp16* uw0, fp16* uw1,
    fp16* wk, fp16* wv, fp16* wo)
{
    long gid = (long)blockIdx.x * 256 + threadIdx.x;
    if (gid < HS_C)  { cvt2_v4(hs,  hsh,  hsl,  gid * 4); return; }
    gid -= HS_C;
    if (gid < ENC_C) { cvt2_v4(enc, ench, encl, gid * 4); return; }
    gid -= ENC_C;
    if (gid < WQ_C)  { cvt1_v4(Wq, wq, gid * 4); return; }
    gid -= WQ_C;
    if (gid < AD_C)  { cvt1_v4(a0dW, dw0, gid * 4); return; }
    gid -= AD_C;
    if (gid < AD_C)  { cvt1_v4(a1dW, dw1, gid * 4); return; }
    gid -= AD_C;
    if (gid < AD_C)  { cvt1_v4(a0uW, uw0, gid * 4); return; }
    gid -= AD_C;
    if (gid < AD_C)  { cvt1_v4(a1uW, uw1, gid * 4); return; }
    gid -= AD_C;
    if (gid < WK_N)  { fold1(Wk, lkA, lkB, wk, DT_, gid); return; }
    gid -= WK_N;
    if (gid < WK_N)  { fold1(Wv, lvA, lvB, wv, DT_, gid); return; }
    gid -= WK_N;
    if (gid < WO_N)  { fold1(Wo, loA, loB, wo, D_, gid); return; }
}

// ---------------------------------------------------------------------------
// Main tensor-core GEMM: C[M,N] = A[M,K] @ W[N,K]^T (+bias), 2-pass fp16 split
// BM=BN=128, BK=64, 2-stage cp.async; optional 2nd problem via blockIdx.z.
// ---------------------------------------------------------------------------
#define SMSH   72                       // halves per smem row (64 + 8 pad)
#define PANELB (128 * SMSH * 2)         // 18432 B
#define STAGEB (3 * PANELB)             // 55296 B
#define GDYN   (2 * STAGEB)             // 110592 B

__global__ void __launch_bounds__(256, 2) mma_gemm_kernel(
    const fp16* __restrict__ Ahi, const fp16* __restrict__ Alo,
    const fp16* __restrict__ Bw,  const fp16* __restrict__ Bw2,
    const float* __restrict__ bias, float* __restrict__ C, float* __restrict__ C2,
    int M, int N, int K)
{
    extern __shared__ fp16 smem_dyn[];
    const unsigned sbase = smem_u32(smem_dyn);

    const fp16* Bsel = (blockIdx.z == 0) ? Bw : Bw2;
    float*      Csel = (blockIdx.z == 0) ? C  : C2;

    const int tid  = threadIdx.x;
    const int warp = tid >> 5;
    const int lane = tid & 31;
    const int bm = blockIdx.y * 128;
    const int bn = blockIdx.x * 128;
    const int wm = (warp >> 1) * 32;
    const int wn = (warp & 1) * 64;

    unsigned dsta[4];
    int a_sz[4];
    size_t a_src[4], b_src[4];
#pragma unroll
    for (int j = 0; j < 4; j++) {
        int c   = tid + 256 * j;
        int row = c >> 3;
        int sl  = c & 7;
        dsta[j] = sbase + (unsigned)(row * SMSH + sl * 8) * 2;
        int gm = bm + row;
        a_sz[j]  = (gm < M) ? 16 : 0;
        int gm_c = (gm < M) ? gm : (M > 0 ? M - 1 : 0);
        a_src[j] = (size_t)gm_c * K + sl * 8;
        b_src[j] = (size_t)(bn + row) * K + sl * 8;
    }

    unsigned a_addr[2], b_addr[4];
#pragma unroll
    for (int i = 0; i < 2; i++) {
        int row = wm + i * 16 + (lane & 15);
        int ko  = (lane >> 4) * 8;
        a_addr[i] = sbase + (unsigned)(row * SMSH + ko) * 2;
    }
#pragma unroll
    for (int jp = 0; jp < 4; jp++) {
        int grp = lane >> 3, lr = lane & 7;
        int row = wn + jp * 16 + ((grp >> 1) * 8) + lr;
        int ko  = (grp & 1) * 8;
        b_addr[jp] = sbase + 2u * PANELB + (unsigned)(row * SMSH + ko) * 2;
    }

    float acc[2][8][4];
#pragma unroll
    for (int i = 0; i < 2; i++)
#pragma unroll
        for (int j = 0; j < 8; j++)
#pragma unroll
            for (int r = 0; r < 4; r++) acc[i][j][r] = 0.f;

    const int KT = K >> 6;

    auto load_stage = [&](int st, int kt) {
        const unsigned so = (unsigned)st * STAGEB;
        const int kb = kt * 64;
#pragma unroll
        for (int j = 0; j < 4; j++) {
            cpa16(dsta[j] + so,              Ahi  + a_src[j] + kb, a_sz[j]);
            cpa16(dsta[j] + so + PANELB,     Alo  + a_src[j] + kb, a_sz[j]);
            cpa16(dsta[j] + so + 2u*PANELB,  Bsel + b_src[j] + kb, 16);
        }
        asm volatile("cp.async.commit_group;\n");
    };

    load_stage(0, 0);

    for (int kt = 0; kt < KT; kt++) {
        asm volatile("cp.async.wait_group 0;\n" ::: "memory");
        __syncthreads();

        if (kt + 1 < KT) load_stage((kt + 1) & 1, kt + 1);

        const unsigned so = (unsigned)(kt & 1) * STAGEB;
#pragma unroll
        for (int ks = 0; ks < 4; ks++) {
            const unsigned kso = so + ks * 32;
            unsigned ah[2][4], al[2][4];
#pragma unroll
            for (int i = 0; i < 2; i++) {
                ldmx4(ah[i][0], ah[i][1], ah[i][2], ah[i][3], a_addr[i] + kso);
                ldmx4(al[i][0], al[i][1], al[i][2], al[i][3], a_addr[i] + kso + PANELB);
            }
#pragma unroll
            for (int jp = 0; jp < 4; jp++) {
                unsigned bw[2][2];
                ldmx4(bw[0][0], bw[0][1], bw[1][0], bw[1][1], b_addr[jp] + kso);
#pragma unroll
                for (int jj = 0; jj < 2; jj++) {
                    int j = jp * 2 + jj;
                    mma_f16(acc[0][j], ah[0], bw[jj]);
                    mma_f16(acc[1][j], ah[1], bw[jj]);
                }
#pragma unroll
                for (int jj = 0; jj < 2; jj++) {
                    int j = jp * 2 + jj;
                    mma_f16(acc[0][j], al[0], bw[jj]);
                    mma_f16(acc[1][j], al[1], bw[jj]);
                }
            }
        }
        __syncthreads();
    }

#pragma unroll
    for (int i = 0; i < 2; i++) {
        int r0 = bm + wm + i * 16 + (lane >> 2);
#pragma unroll
        for (int j = 0; j < 8; j++) {
            int col = bn + wn + j * 8 + (lane & 3) * 2;
            float b0 = bias ? bias[col] : 0.f;
            float b1 = bias ? bias[col + 1] : 0.f;
            if (r0 < M) {
                float2 v = make_float2(acc[i][j][0] + b0, acc[i][j][1] + b1);
                *(float2*)(Csel + (size_t)r0 * N + col) = v;
            }
            if (r0 + 8 < M) {
                float2 v = make_float2(acc[i][j][2] + b0, acc[i][j][3] + b1);
                *(float2*)(Csel + (size_t)(r0 + 8) * N + col) = v;
            }
        }
    }
}

// ---------------------------------------------------------------------------
// Adapter down-proj GEMM: H[M,64] = gelu( X[M,1280] @ dW[64,1280]^T + db )
// 2-pass fp16 split on X (hi/lo), fp16 weights, fp16 H output.
// BM=128, BN=64, BK=64; blockIdx.z selects adapter 0/1.
// ---------------------------------------------------------------------------
#define BPANELB (64 * SMSH * 2)              // 9216 B
#define STAGE_D (2 * PANELB + BPANELB)       // 46080 B
#define GDYN_D  (2 * STAGE_D)                // 92160 B

__global__ void __launch_bounds__(256, 2) adapter_down_kernel(
    const fp16* __restrict__ F0h, const fp16* __restrict__ F0l,
    const fp16* __restrict__ F1h, const fp16* __restrict__ F1l,
    const fp16* __restrict__ dw0, const fp16* __restrict__ dw1,
    const float* __restrict__ db0, const float* __restrict__ db1,
    fp16* __restrict__ Hbuf)
{
    extern __shared__ fp16 smem_dyn[];
    const unsigned sbase = smem_u32(smem_dyn);

    const int z = blockIdx.z;
    const fp16* Ah = z ? F1h : F0h;
    const fp16* Al = z ? F1l : F0l;
    const fp16* Bw = z ? dw1 : dw0;
    const float* db = z ? db1 : db0;
    fp16* Hout = Hbuf + (size_t)z * M_BS * RAD_;

    const int tid  = threadIdx.x;
    const int warp = tid >> 5;
    const int lane = tid & 31;
    const int bm = blockIdx.y * 128;
    const int K = D_;

    unsigned dsta[4];
    size_t a_src[4];
#pragma unroll
    for (int j = 0; j < 4; j++) {
        int c   = tid + 256 * j;
        int row = c >> 3;
        int sl  = c & 7;
        dsta[j] = sbase + (unsigned)(row * SMSH + sl * 8) * 2;
        a_src[j] = (size_t)(bm + row) * K + sl * 8;
    }
    unsigned dstb[2];
    size_t b_src[2];
#pragma unroll
    for (int j = 0; j < 2; j++) {
        int c   = tid + 256 * j;
        int row = c >> 3;           // 0..63
        int sl  = c & 7;
        dstb[j] = sbase + 2u * PANELB + (unsigned)(row * SMSH + sl * 8) * 2;
        b_src[j] = (size_t)row * K + sl * 8;
    }

    const int wm = (warp >> 1) * 32;
    const int wn = (warp & 1) * 32;

    unsigned a_addr[2], b_addr[2];
#pragma unroll
    for (int i = 0; i < 2; i++) {
        int row = wm + i * 16 + (lane & 15);
        int ko  = (lane >> 4) * 8;
        a_addr[i] = sbase + (unsigned)(row * SMSH + ko) * 2;
    }
#pragma unroll
    for (int jp = 0; jp < 2; jp++) {
        int grp = lane >> 3, lr = lane & 7;
        int row = wn + jp * 16 + ((grp >> 1) * 8) + lr;
        int ko  = (grp & 1) * 8;
        b_addr[jp] = sbase + 2u * PANELB + (unsigned)(row * SMSH + ko) * 2;
    }

    float acc[2][4][4];
#pragma unroll
    for (int i = 0; i < 2; i++)
#pragma unroll
        for (int j = 0; j < 4; j++)
#pragma unroll
            for (int r = 0; r < 4; r++) acc[i][j][r] = 0.f;

    const int KT = K >> 6;   // 20

    auto load_stage = [&](int st, int kt) {
        const unsigned so = (unsigned)st * STAGE_D;
        const int kb = kt * 64;
#pragma unroll
        for (int j = 0; j < 4; j++) {
            cpa16(dsta[j] + so,          Ah + a_src[j] + kb, 16);
            cpa16(dsta[j] + so + PANELB, Al + a_src[j] + kb, 16);
        }
#pragma unroll
        for (int j = 0; j < 2; j++)
            cpa16(dstb[j] + so, Bw + b_src[j] + kb, 16);
        asm volatile("cp.async.commit_group;\n");
    };

    load_stage(0, 0);

    for (int kt = 0; kt < KT; kt++) {
        asm volatile("cp.async.wait_group 0;\n" ::: "memory");
        __syncthreads();

        if (kt + 1 < KT) load_stage((kt + 1) & 1, kt + 1);

        const unsigned so = (unsigned)(kt & 1) * STAGE_D;
#pragma unroll
        for (int ks = 0; ks < 4; ks++) {
            const unsigned kso = so + ks * 32;
            unsigned ah[2][4], al[2][4];
#pragma unroll
            for (int i = 0; i < 2; i++) {
                ldmx4(ah[i][0], ah[i][1], ah[i][2], ah[i][3], a_addr[i] + kso);
                ldmx4(al[i][0], al[i][1], al[i][2], al[i][3], a_addr[i] + kso + PANELB);
            }
#pragma unroll
            for (int jp = 0; jp < 2; jp++) {
                unsigned bw[2][2];
                ldmx4(bw[0][0], bw[0][1], bw[1][0], bw[1][1], b_addr[jp] + kso);
#pragma unroll
                for (int jj = 0; jj < 2; jj++) {
                    int j = jp * 2 + jj;
                    mma_f16(acc[0][j], ah[0], bw[jj]);
                    mma_f16(acc[1][j], ah[1], bw[jj]);
                }
#pragma unroll
                for (int jj = 0; jj < 2; jj++) {
                    int j = jp * 2 + jj;
                    mma_f16(acc[0][j], al[0], bw[jj]);
                    mma_f16(acc[1][j], al[1], bw[jj]);
                }
            }
        }
        __syncthreads();
    }

#pragma unroll
    for (int i = 0; i < 2; i++) {
        int r0 = bm + wm + i * 16 + (lane >> 2);
#pragma unroll
        for (int j = 0; j < 4; j++) {
            int col = wn + j * 8 + (lane & 3) * 2;
            float b0 = db[col], b1 = db[col + 1];
            {
                float v0 = gelu_exact(acc[i][j][0] + b0);
                float v1 = gelu_exact(acc[i][j][1] + b1);
                __half2 hv = __floats2half2_rn(v0, v1);
                *(__half2*)(Hout + (size_t)r0 * RAD_ + col) = hv;
            }
            {
                float v0 = gelu_exact(acc[i][j][2] + b0);
                float v1 = gelu_exact(acc[i][j][3] + b1);
                __half2 hv = __floats2half2_rn(v0, v1);
                *(__half2*)(Hout + (size_t)(r0 + 8) * RAD_ + col) = hv;
            }
        }
    }
}

// ---------------------------------------------------------------------------
// Adapter up-proj GEMM: out[M,1280] = X + ( H[M,64] @ uW[1280,64]^T + ub )
// single-pass fp16 (K=64 exact in fp32 accum); X reconstructed as hi+lo.
// BM=BN=128, K=64 (single stage); blockIdx.z selects adapter.
// ---------------------------------------------------------------------------
__global__ void __launch_bounds__(256, 2) adapter_up_kernel(
    const fp16* __restrict__ Hbuf,
    const fp16* __restrict__ uw0, const fp16* __restrict__ uw1,
    const float* __restrict__ ub0, const float* __restrict__ ub1,
    const fp16* __restrict__ F0h, const fp16* __restrict__ F0l,
    const fp16* __restrict__ F1h, const fp16* __restrict__ F1l,
    float* __restrict__ out)
{
    __shared__ fp16 smem_up[2 * 128 * SMSH];
    const unsigned sbase = smem_u32(smem_up);

    const int z = blockIdx.z;
    const fp16* A  = Hbuf + (size_t)z * M_BS * RAD_;
    const fp16* Bw = z ? uw1 : uw0;
    const float* ub = z ? ub1 : ub0;
    const fp16* Fh = z ? F1h : F0h;
    const fp16* Fl = z ? F1l : F0l;
    float* C = out + (size_t)(z + 1) * OFF_;

    const int tid  = threadIdx.x;
    const int warp = tid >> 5;
    const int lane = tid & 31;
    const int bm = blockIdx.y * 128;
    const int bn = blockIdx.x * 128;

    // load A tile [128,64] and B tile [128,64] (K=64 => 8 segs of 16B)
#pragma unroll
    for (int j = 0; j < 4; j++) {
        int c   = tid + 256 * j;
        int row = c >> 3;
        int sl  = c & 7;
        *(uint4*)(smem_up + row * SMSH + sl * 8) =
            *(const uint4*)(A + (size_t)(bm + row) * RAD_ + sl * 8);
        *(uint4*)(smem_up + 128 * SMSH + row * SMSH + sl * 8) =
            *(const uint4*)(Bw + (size_t)(bn + row) * RAD_ + sl * 8);
    }
    __syncthreads();

    const int wm = (warp >> 1) * 32;
    const int wn = (warp & 1) * 64;

    unsigned a_addr[2], b_addr[4];
#pragma unroll
    for (int i = 0; i < 2; i++) {
        int row = wm + i * 16 + (lane & 15);
        int ko  = (lane >> 4) * 8;
        a_addr[i] = sbase + (unsigned)(row * SMSH + ko) * 2;
    }
#pragma unroll
    for (int jp = 0; jp < 4; jp++) {
        int grp = lane >> 3, lr = lane & 7;
        int row = wn + jp * 16 + ((grp >> 1) * 8) + lr;
        int ko  = (grp & 1) * 8;
        b_addr[jp] = sbase + (unsigned)(128 * SMSH + row * SMSH + ko) * 2;
    }

    float acc[2][8][4];
#pragma unroll
    for (int i = 0; i < 2; i++)
#pragma unroll
        for (int j = 0; j < 8; j++)
#pragma unroll
            for (int r = 0; r < 4; r++) acc[i][j][r] = 0.f;

#pragma unroll
    for (int ks = 0; ks < 4; ks++) {
        const unsigned kso = ks * 32;
        unsigned ah[2][4];
#pragma unroll
        for (int i = 0; i < 2; i++)
            ldmx4(ah[i][0], ah[i][1], ah[i][2], ah[i][3], a_addr[i] + kso);
#pragma unroll
        for (int jp = 0; jp < 4; jp++) {
            unsigned bw[2][2];
            ldmx4(bw[0][0], bw[0][1], bw[1][0], bw[1][1], b_addr[jp] + kso);
#pragma unroll
            for (int jj = 0; jj < 2; jj++) {
                int j = jp * 2 + jj;
                mma_f16(acc[0][j], ah[0], bw[jj]);
                mma_f16(acc[1][j], ah[1], bw[jj]);
            }
        }
    }

#pragma unroll
    for (int i = 0; i < 2; i++) {
        int r0 = bm + wm + i * 16 + (lane >> 2);
#pragma unroll
        for (int j = 0; j < 8; j++) {
            int col = bn + wn + j * 8 + (lane & 3) * 2;
            float u0 = ub[col], u1 = ub[col + 1];
#pragma unroll
            for (int rr = 0; rr < 2; rr++) {
                int r = r0 + rr * 8;
                __half2 xh = *(const __half2*)(Fh + (size_t)r * D_ + col);
                __half2 xl = *(const __half2*)(Fl + (size_t)r * D_ + col);
                float x0 = __half2float(__low2half(xh)) + __half2float(__low2half(xl));
                float x1 = __half2float(__high2half(xh)) + __half2float(__high2half(xl));
                float2 v = make_float2(acc[i][j][rr*2+0] + u0 + x0,
                                       acc[i][j][rr*2+1] + u1 + x1);
                *(float2*)(C + (size_t)r * D_ + col) = v;
            }
        }
    }
}

// ---------------------------------------------------------------------------
// Attention, templated on TKV; writes fp16 hi/lo split outputs.
// ---------------------------------------------------------------------------
template<int TKV>
__global__ void __launch_bounds__(256) attn_kernel_t(
    const float* __restrict__ q, const float* __restrict__ k,
    const float* __restrict__ v, const int* __restrict__ toks,
    int maybe64, fp16* __restrict__ outH, fp16* __restrict__ outL)
{
    constexpr int NS = (TKV + 31) / 32;
    extern __shared__ float sm[];
    float* Ks = sm;
    float* Vs = sm + TKV * HD_;

    const int b  = blockIdx.z;
    const int h  = blockIdx.y;
    const int s0 = blockIdx.x * 64;
    const int tid = threadIdx.x;

    int is64 = 0;
    if (toks && maybe64)
        is64 = (toks[1] == 0 && toks[3] == 0 && toks[5] == 0 && toks[7] == 0);

    if (toks) {
        for (int i = tid; i < TKV * HD_; i += 256) {
            int t = i / HD_;
            int d = i - t * HD_;
            int trow = is64 ? toks[2 * t] : toks[t];
            size_t gidx = ((size_t)b * T_ + trow) * D_ + h * HD_ + d;
            Ks[i] = k[gidx];
            Vs[i] = v[gidx];
        }
    } else {
        const float* kb = k + (size_t)b * T_ * D_ + h * HD_;
        const float* vb = v + (size_t)b * T_ * D_ + h * HD_;
        for (int i = tid * 4; i < TKV * HD_; i += 1024) {
            int t = i / HD_;
            int d = i - t * HD_;
            *(float4*)(Ks + i) = *(const float4*)(kb + (size_t)t * D_ + d);
            *(float4*)(Vs + i) = *(const float4*)(vb + (size_t)t * D_ + d);
        }
    }
    __syncthreads();

    const int warp = tid >> 5;
    const int lane = tid & 31;
    const float scale = 0.07905694150420949f;
    const unsigned FULL = 0xffffffffu;

    for (int itq = 0; itq < 8; itq++) {
        int s = s0 + warp * 8 + itq;
        size_t base = ((size_t)b * S_ + s) * D_ + h * HD_;

        float qr[5];
#pragma unroll
        for (int j = 0; j < 5; j++) qr[j] = q[base + lane + 32 * j];

        float sc[NS];
#pragma unroll
        for (int n = 0; n < NS; n++) sc[n] = 0.f;

#pragma unroll 4
        for (int t = 0; t < TKV; t++) {
            float p = 0.f;
            const float* kr = Ks + t * HD_;
#pragma unroll
            for (int j = 0; j < 5; j++) p += qr[j] * kr[lane + 32 * j];
#pragma unroll
            for (int off = 16; off; off >>= 1)
                p += __shfl_xor_sync(FULL, p, off);
            if ((t & 31) == lane) sc[t >> 5] = p * scale;
        }

        float m = -1e30f;
#pragma unroll
        for (int n = 0; n < NS; n++)
            if (n * 32 + lane < TKV) m = fmaxf(m, sc[n]);
#pragma unroll
        for (int off = 16; off; off >>= 1)
            m = fmaxf(m, __shfl_xor_sync(FULL, m, off));

        float ssum = 0.f;
#pragma unroll
        for (int n = 0; n < NS; n++) {
            sc[n] = (n * 32 + lane < TKV) ? expf(sc[n] - m) : 0.f;
            ssum += sc[n];
        }
#pragma unroll
        for (int off = 16; off; off >>= 1)
            ssum += __shfl_xor_sync(FULL, ssum, off);
        float inv = 1.f / ssum;
#pragma unroll
        for (int n = 0; n < NS; n++) sc[n] *= inv;

        float o[5] = {0.f, 0.f, 0.f, 0.f, 0.f};
#pragma unroll 4
        for (int t = 0; t < TKV; t++) {
            float p = __shfl_sync(FULL, sc[t >> 5], t & 31);
            const float* vr = Vs + t * HD_;
#pragma unroll
            for (int j = 0; j < 5; j++) o[j] += p * vr[lane + 32 * j];
        }

#pragma unroll
        for (int j = 0; j < 5; j++) {
            fp16 hh, ll; split_f16(o[j], hh, ll);
            outH[base + lane + 32 * j] = hh;
            outL[base + lane + 32 * j] = ll;
        }
    }
}

// ---------------------------------------------------------------------------
// Launch
// ---------------------------------------------------------------------------
extern "C" void kernel_launch(void* const* d_in, const int* in_sizes, int n_in,
                              void* d_out, int out_size)
{
    const float* hs    = (const float*)d_in[0];
    const float* enc   = (const float*)d_in[1];
    const int*   e0    = (const int*)  d_in[2];
    const int*   e1    = (const int*)  d_in[3];
    const float* Wq    = (const float*)d_in[4];
    const float* Wk    = (const float*)d_in[5];
    const float* Wv    = (const float*)d_in[6];
    const float* Wo    = (const float*)d_in[7];
    const float* bo    = (const float*)d_in[8];
    const float* lkA   = (const float*)d_in[9];
    const float* lkB   = (const float*)d_in[10];
    const float* lvA   = (const float*)d_in[11];
    const float* lvB   = (const float*)d_in[12];
    const float* loA   = (const float*)d_in[13];
    const float* loB   = (const float*)d_in[14];
    const float* a0dW  = (const float*)d_in[15];
    const float* a0db  = (const float*)d_in[16];
    const float* a0uW  = (const float*)d_in[17];
    const float* a0ub  = (const float*)d_in[18];
    const float* a1dW  = (const float*)d_in[19];
    const float* a1db  = (const float*)d_in[20];
    const float* a1uW  = (const float*)d_in[21];
    const float* a1ub  = (const float*)d_in[22];

    float *qp, *kp, *vp;
    fp16 *hsh, *hsl, *fgh, *fgl, *f0h, *f0l, *f1h, *f1l, *ench, *encl;
    fp16 *wq, *wo, *wk, *wv, *dw0, *dw1, *uw0, *uw1, *Hb;
    cudaGetSymbolAddress((void**)&qp,   g_q);
    cudaGetSymbolAddress((void**)&kp,   g_k);
    cudaGetSymbolAddress((void**)&vp,   g_v);
    cudaGetSymbolAddress((void**)&hsh,  g_hs_hi);
    cudaGetSymbolAddress((void**)&hsl,  g_hs_lo);
    cudaGetSymbolAddress((void**)&fgh,  g_fg_hi);
    cudaGetSymbolAddress((void**)&fgl,  g_fg_lo);
    cudaGetSymbolAddress((void**)&f0h,  g_f0_hi);
    cudaGetSymbolAddress((void**)&f0l,  g_f0_lo);
    cudaGetSymbolAddress((void**)&f1h,  g_f1_hi);
    cudaGetSymbolAddress((void**)&f1l,  g_f1_lo);
    cudaGetSymbolAddress((void**)&ench, g_enc_hi);
    cudaGetSymbolAddress((void**)&encl, g_enc_lo);
    cudaGetSymbolAddress((void**)&wq,   g_wq);
    cudaGetSymbolAddress((void**)&wo,   g_wo);
    cudaGetSymbolAddress((void**)&wk,   g_wk);
    cudaGetSymbolAddress((void**)&wv,   g_wv);
    cudaGetSymbolAddress((void**)&dw0,  g_dw0);
    cudaGetSymbolAddress((void**)&dw1,  g_dw1);
    cudaGetSymbolAddress((void**)&uw0,  g_uw0);
    cudaGetSymbolAddress((void**)&uw1,  g_uw1);
    cudaGetSymbolAddress((void**)&Hb,   g_H);

    float* out = (float*)d_out;

    cudaFuncSetAttribute(mma_gemm_kernel,
                         cudaFuncAttributeMaxDynamicSharedMemorySize, GDYN);
    cudaFuncSetAttribute(adapter_down_kernel,
                         cudaFuncAttributeMaxDynamicSharedMemorySize, GDYN_D);
    cudaFuncSetAttribute(attn_kernel_t<77>,
                         cudaFuncAttributeMaxDynamicSharedMemorySize, 101376);

    // 1: fused prep (all converts + folds)
    long prep_blocks = (PREP_TOT + 255) / 256;
    prep_kernel<<<(unsigned)prep_blocks, 256>>>(
        hs, enc, Wq, a0dW, a1dW, a0uW, a1uW,
        Wk, lkA, lkB, Wv, lvA, lvB, Wo, loA, loB,
        hsh, hsl, ench, encl, wq, dw0, dw1, uw0, uw1, wk, wv, wo);

    // 2: q projection
    dim3 gq(D_ / 128, M_BS / 128, 1);
    mma_gemm_kernel<<<gq, 256, GDYN>>>(hsh, hsl, wq, nullptr, nullptr,
                                       qp, nullptr, M_BS, D_, D_);

    // 3: merged k+v projections
    dim3 gkv(D_ / 128, (M_BT + 127) / 128, 2);
    mma_gemm_kernel<<<gkv, 256, GDYN>>>(ench, encl, wk, wv, nullptr,
                                        kp, vp, M_BT, D_, DT_);

    // 4: global attention  <-- ncu capture slot
    dim3 ga(S_ / 64, H_, B_);
    attn_kernel_t<77><<<ga, 256, (size_t)T_ * HD_ * 2 * sizeof(float)>>>(
        qp, kp, vp, nullptr, 0, fgh, fgl);

    // 5-6: entity attentions
    attn_kernel_t<8><<<ga, 256, (size_t)8 * HD_ * 2 * sizeof(float)>>>(
        qp, kp, vp, e0, 1, f0h, f0l);
    attn_kernel_t<12><<<ga, 256, (size_t)12 * HD_ * 2 * sizeof(float)>>>(
        qp, kp, vp, e1, 0, f1h, f1l);

    // 7: adapter down (both adapters via z)
    dim3 gd(1, M_BS / 128, 2);
    adapter_down_kernel<<<gd, 256, GDYN_D>>>(f0h, f0l, f1h, f1l,
                                             dw0, dw1, a0db, a1db, Hb);

    // 8: adapter up (both adapters via z) -> F_0 / F_1 output slots
    dim3 gu(D_ / 128, M_BS / 128, 2);
    adapter_up_kernel<<<gu, 256>>>(Hb, uw0, uw1, a0ub, a1ub,
                                   f0h, f0l, f1h, f1l, out);

    // 9: output projection -> out slot
    mma_gemm_kernel<<<gq, 256, GDYN>>>(fgh, fgl, wo, nullptr, bo,
                                       out, nullptr, M_BS, D_, D_);
}

// round 12
// speedup vs baseline: 4.9538x; 1.2252x over previous
#include <cuda_runtime.h>
#include <cuda_fp16.h>
#include <math.h>
#include <stdint.h>
#include <stddef.h>

// ---------------------------------------------------------------------------
// Problem constants
// ---------------------------------------------------------------------------
#define B_   4
#define S_   4096
#define T_   77
#define D_   1280
#define DT_  768
#define H_   8
#define HD_  160
#define RAD_ 64
#define M_BS (B_*S_)   // 16384
#define M_BT (B_*T_)   // 308
#define OFF_ ((size_t)M_BS * D_)

typedef __half fp16;

// ---------------------------------------------------------------------------
// Device scratch
// ---------------------------------------------------------------------------
__device__ float g_q  [M_BS * D_];
__device__ float g_k  [M_BT * D_];
__device__ float g_v  [M_BT * D_];

__device__ fp16 g_hs_hi [M_BS * D_];
__device__ fp16 g_hs_lo [M_BS * D_];
__device__ fp16 g_fg_hi [M_BS * D_];
__device__ fp16 g_fg_lo [M_BS * D_];
__device__ fp16 g_f0_hi [M_BS * D_];
__device__ fp16 g_f0_lo [M_BS * D_];
__device__ fp16 g_f1_hi [M_BS * D_];
__device__ fp16 g_f1_lo [M_BS * D_];
__device__ fp16 g_enc_hi[M_BT * DT_];
__device__ fp16 g_enc_lo[M_BT * DT_];
__device__ fp16 g_wq [D_ * D_];
__device__ fp16 g_wo [D_ * D_];
__device__ fp16 g_wk [D_ * DT_];
__device__ fp16 g_wv [D_ * DT_];
__device__ fp16 g_dw0[RAD_ * D_];
__device__ fp16 g_dw1[RAD_ * D_];
__device__ fp16 g_uw0[D_ * RAD_];
__device__ fp16 g_uw1[D_ * RAD_];
__device__ fp16 g_H  [2 * M_BS * RAD_];

// ---------------------------------------------------------------------------
// helpers
// ---------------------------------------------------------------------------
__device__ __forceinline__ unsigned smem_u32(const void* p) {
    return (unsigned)__cvta_generic_to_shared(p);
}
__device__ __forceinline__ void cpa16(unsigned dst, const fp16* src, int sz) {
    asm volatile("cp.async.cg.shared.global [%0], [%1], 16, %2;\n"
                 :: "r"(dst), "l"(src), "r"(sz));
}
__device__ __forceinline__ void ldmx4(unsigned& r0, unsigned& r1, unsigned& r2, unsigned& r3, unsigned addr) {
    asm volatile("ldmatrix.sync.aligned.m8n8.x4.shared.b16 {%0,%1,%2,%3}, [%4];"
                 : "=r"(r0), "=r"(r1), "=r"(r2), "=r"(r3) : "r"(addr));
}
__device__ __forceinline__ void mma_f16(float* d, const unsigned* a, const unsigned* b) {
    asm volatile(
        "mma.sync.aligned.m16n8k16.row.col.f32.f16.f16.f32 "
        "{%0,%1,%2,%3}, {%4,%5,%6,%7}, {%8,%9}, {%0,%1,%2,%3};"
        : "+f"(d[0]), "+f"(d[1]), "+f"(d[2]), "+f"(d[3])
        : "r"(a[0]), "r"(a[1]), "r"(a[2]), "r"(a[3]), "r"(b[0]), "r"(b[1]));
}
__device__ __forceinline__ void split_f16(float x, fp16& hi, fp16& lo) {
    hi = __float2half_rn(x);
    lo = __float2half_rn(x - __half2float(hi));
}
__device__ __forceinline__ float gelu_exact(float x) {
    return 0.5f * x * (1.f + erff(x * 0.7071067811865475f));
}

// ---------------------------------------------------------------------------
// prep: all converts + LoRA folds fused (region-dispatched)
// ---------------------------------------------------------------------------
#define HS_C   5242880L   // M_BS*D_/4
#define ENC_C  59136L     // M_BT*DT_/4
#define WQ_C   409600L    // D_*D_/4
#define AD_C   20480L     // RAD_*D_/4 (per array)
#define WK_N   983040L    // D_*DT_
#define WO_N   1638400L   // D_*D_
#define PREP_TOT (HS_C + ENC_C + WQ_C + 4*AD_C + 2*WK_N + WO_N)

__device__ __forceinline__ void cvt2_v4(const float* x, fp16* hi, fp16* lo, long i) {
    float4 v = *(const float4*)(x + i);
    fp16 h0,l0,h1,l1,h2,l2,h3,l3;
    split_f16(v.x,h0,l0); split_f16(v.y,h1,l1); split_f16(v.z,h2,l2); split_f16(v.w,h3,l3);
    hi[i]=h0; hi[i+1]=h1; hi[i+2]=h2; hi[i+3]=h3;
    lo[i]=l0; lo[i+1]=l1; lo[i+2]=l2; lo[i+3]=l3;
}
__device__ __forceinline__ void cvt1_v4(const float* x, fp16* w, long i) {
    float4 v = *(const float4*)(x + i);
    w[i]   = __float2half_rn(v.x); w[i+1] = __float2half_rn(v.y);
    w[i+2] = __float2half_rn(v.z); w[i+3] = __float2half_rn(v.w);
}
__device__ __forceinline__ void fold1(const float* W, const float* A, const float* Bm,
                                      fp16* w, int K, long i) {
    int n = (int)(i / K);
    int k = (int)(i - (long)n * K);
    float acc = W[i];
#pragma unroll
    for (int r = 0; r < 4; r++)
        acc += 0.25f * Bm[n * 4 + r] * A[r * K + k];
    w[i] = __float2half_rn(acc);
}

__global__ void prep_kernel(
    const float* __restrict__ hs, const float* __restrict__ enc, const float* __restrict__ Wq,
    const float* __restrict__ a0dW, const float* __restrict__ a1dW,
    const float* __restrict__ a0uW, const float* __restrict__ a1uW,
    const float* __restrict__ Wk, const float* __restrict__ lkA, const float* __restrict__ lkB,
    const float* __restrict__ Wv, const float* __restrict__ lvA, const float* __restrict__ lvB,
    const float* __restrict__ Wo, const float* __restrict__ loA, const float* __restrict__ loB,
    fp16* hsh, fp16* hsl, fp16* ench, fp16* encl, fp16* wq,
    fp16* dw0, fp16* dw1, fp16* uw0, fp16* uw1,
    fp16* wk, fp16* wv, fp16* wo)
{
    long gid = (long)blockIdx.x * 256 + threadIdx.x;
    if (gid < HS_C)  { cvt2_v4(hs,  hsh,  hsl,  gid * 4); return; }
    gid -= HS_C;
    if (gid < ENC_C) { cvt2_v4(enc, ench, encl, gid * 4); return; }
    gid -= ENC_C;
    if (gid < WQ_C)  { cvt1_v4(Wq, wq, gid * 4); return; }
    gid -= WQ_C;
    if (gid < AD_C)  { cvt1_v4(a0dW, dw0, gid * 4); return; }
    gid -= AD_C;
    if (gid < AD_C)  { cvt1_v4(a1dW, dw1, gid * 4); return; }
    gid -= AD_C;
    if (gid < AD_C)  { cvt1_v4(a0uW, uw0, gid * 4); return; }
    gid -= AD_C;
    if (gid < AD_C)  { cvt1_v4(a1uW, uw1, gid * 4); return; }
    gid -= AD_C;
    if (gid < WK_N)  { fold1(Wk, lkA, lkB, wk, DT_, gid); return; }
    gid -= WK_N;
    if (gid < WK_N)  { fold1(Wv, lvA, lvB, wv, DT_, gid); return; }
    gid -= WK_N;
    if (gid < WO_N)  { fold1(Wo, loA, loB, wo, D_, gid); return; }
}

// ---------------------------------------------------------------------------
// Main tensor-core GEMM: C[M,N] = A[M,K] @ W[N,K]^T (+bias), 2-pass fp16 split
// ---------------------------------------------------------------------------
#define SMSH   72                       // halves per smem row (64 + 8 pad)
#define PANELB (128 * SMSH * 2)         // 18432 B
#define STAGEB (3 * PANELB)             // 55296 B
#define GDYN   (2 * STAGEB)             // 110592 B

__global__ void __launch_bounds__(256, 2) mma_gemm_kernel(
    const fp16* __restrict__ Ahi, const fp16* __restrict__ Alo,
    const fp16* __restrict__ Bw,  const fp16* __restrict__ Bw2,
    const float* __restrict__ bias, float* __restrict__ C, float* __restrict__ C2,
    int M, int N, int K)
{
    extern __shared__ fp16 smem_dyn[];
    const unsigned sbase = smem_u32(smem_dyn);

    const fp16* Bsel = (blockIdx.z == 0) ? Bw : Bw2;
    float*      Csel = (blockIdx.z == 0) ? C  : C2;

    const int tid  = threadIdx.x;
    const int warp = tid >> 5;
    const int lane = tid & 31;
    const int bm = blockIdx.y * 128;
    const int bn = blockIdx.x * 128;
    const int wm = (warp >> 1) * 32;
    const int wn = (warp & 1) * 64;

    unsigned dsta[4];
    int a_sz[4];
    size_t a_src[4], b_src[4];
#pragma unroll
    for (int j = 0; j < 4; j++) {
        int c   = tid + 256 * j;
        int row = c >> 3;
        int sl  = c & 7;
        dsta[j] = sbase + (unsigned)(row * SMSH + sl * 8) * 2;
        int gm = bm + row;
        a_sz[j]  = (gm < M) ? 16 : 0;
        int gm_c = (gm < M) ? gm : (M > 0 ? M - 1 : 0);
        a_src[j] = (size_t)gm_c * K + sl * 8;
        b_src[j] = (size_t)(bn + row) * K + sl * 8;
    }

    unsigned a_addr[2], b_addr[4];
#pragma unroll
    for (int i = 0; i < 2; i++) {
        int row = wm + i * 16 + (lane & 15);
        int ko  = (lane >> 4) * 8;
        a_addr[i] = sbase + (unsigned)(row * SMSH + ko) * 2;
    }
#pragma unroll
    for (int jp = 0; jp < 4; jp++) {
        int grp = lane >> 3, lr = lane & 7;
        int row = wn + jp * 16 + ((grp >> 1) * 8) + lr;
        int ko  = (grp & 1) * 8;
        b_addr[jp] = sbase + 2u * PANELB + (unsigned)(row * SMSH + ko) * 2;
    }

    float acc[2][8][4];
#pragma unroll
    for (int i = 0; i < 2; i++)
#pragma unroll
        for (int j = 0; j < 8; j++)
#pragma unroll
            for (int r = 0; r < 4; r++) acc[i][j][r] = 0.f;

    const int KT = K >> 6;

    auto load_stage = [&](int st, int kt) {
        const unsigned so = (unsigned)st * STAGEB;
        const int kb = kt * 64;
#pragma unroll
        for (int j = 0; j < 4; j++) {
            cpa16(dsta[j] + so,              Ahi  + a_src[j] + kb, a_sz[j]);
            cpa16(dsta[j] + so + PANELB,     Alo  + a_src[j] + kb, a_sz[j]);
            cpa16(dsta[j] + so + 2u*PANELB,  Bsel + b_src[j] + kb, 16);
        }
        asm volatile("cp.async.commit_group;\n");
    };

    load_stage(0, 0);

    for (int kt = 0; kt < KT; kt++) {
        asm volatile("cp.async.wait_group 0;\n" ::: "memory");
        __syncthreads();

        if (kt + 1 < KT) load_stage((kt + 1) & 1, kt + 1);

        const unsigned so = (unsigned)(kt & 1) * STAGEB;
#pragma unroll
        for (int ks = 0; ks < 4; ks++) {
            const unsigned kso = so + ks * 32;
            unsigned ah[2][4], al[2][4];
#pragma unroll
            for (int i = 0; i < 2; i++) {
                ldmx4(ah[i][0], ah[i][1], ah[i][2], ah[i][3], a_addr[i] + kso);
                ldmx4(al[i][0], al[i][1], al[i][2], al[i][3], a_addr[i] + kso + PANELB);
            }
#pragma unroll
            for (int jp = 0; jp < 4; jp++) {
                unsigned bw[2][2];
                ldmx4(bw[0][0], bw[0][1], bw[1][0], bw[1][1], b_addr[jp] + kso);
#pragma unroll
                for (int jj = 0; jj < 2; jj++) {
                    int j = jp * 2 + jj;
                    mma_f16(acc[0][j], ah[0], bw[jj]);
                    mma_f16(acc[1][j], ah[1], bw[jj]);
                }
#pragma unroll
                for (int jj = 0; jj < 2; jj++) {
                    int j = jp * 2 + jj;
                    mma_f16(acc[0][j], al[0], bw[jj]);
                    mma_f16(acc[1][j], al[1], bw[jj]);
                }
            }
        }
        __syncthreads();
    }

#pragma unroll
    for (int i = 0; i < 2; i++) {
        int r0 = bm + wm + i * 16 + (lane >> 2);
#pragma unroll
        for (int j = 0; j < 8; j++) {
            int col = bn + wn + j * 8 + (lane & 3) * 2;
            float b0 = bias ? bias[col] : 0.f;
            float b1 = bias ? bias[col + 1] : 0.f;
            if (r0 < M) {
                float2 v = make_float2(acc[i][j][0] + b0, acc[i][j][1] + b1);
                *(float2*)(Csel + (size_t)r0 * N + col) = v;
            }
            if (r0 + 8 < M) {
                float2 v = make_float2(acc[i][j][2] + b0, acc[i][j][3] + b1);
                *(float2*)(Csel + (size_t)(r0 + 8) * N + col) = v;
            }
        }
    }
}

// ---------------------------------------------------------------------------
// Adapter down-proj GEMM: H[M,64] = gelu( X[M,1280] @ dW[64,1280]^T + db )
// ---------------------------------------------------------------------------
#define BPANELB (64 * SMSH * 2)              // 9216 B
#define STAGE_D (2 * PANELB + BPANELB)       // 46080 B
#define GDYN_D  (2 * STAGE_D)                // 92160 B

__global__ void __launch_bounds__(256, 2) adapter_down_kernel(
    const fp16* __restrict__ F0h, const fp16* __restrict__ F0l,
    const fp16* __restrict__ F1h, const fp16* __restrict__ F1l,
    const fp16* __restrict__ dw0, const fp16* __restrict__ dw1,
    const float* __restrict__ db0, const float* __restrict__ db1,
    fp16* __restrict__ Hbuf)
{
    extern __shared__ fp16 smem_dyn[];
    const unsigned sbase = smem_u32(smem_dyn);

    const int z = blockIdx.z;
    const fp16* Ah = z ? F1h : F0h;
    const fp16* Al = z ? F1l : F0l;
    const fp16* Bw = z ? dw1 : dw0;
    const float* db = z ? db1 : db0;
    fp16* Hout = Hbuf + (size_t)z * M_BS * RAD_;

    const int tid  = threadIdx.x;
    const int warp = tid >> 5;
    const int lane = tid & 31;
    const int bm = blockIdx.y * 128;
    const int K = D_;

    unsigned dsta[4];
    size_t a_src[4];
#pragma unroll
    for (int j = 0; j < 4; j++) {
        int c   = tid + 256 * j;
        int row = c >> 3;
        int sl  = c & 7;
        dsta[j] = sbase + (unsigned)(row * SMSH + sl * 8) * 2;
        a_src[j] = (size_t)(bm + row) * K + sl * 8;
    }
    unsigned dstb[2];
    size_t b_src[2];
#pragma unroll
    for (int j = 0; j < 2; j++) {
        int c   = tid + 256 * j;
        int row = c >> 3;
        int sl  = c & 7;
        dstb[j] = sbase + 2u * PANELB + (unsigned)(row * SMSH + sl * 8) * 2;
        b_src[j] = (size_t)row * K + sl * 8;
    }

    const int wm = (warp >> 1) * 32;
    const int wn = (warp & 1) * 32;

    unsigned a_addr[2], b_addr[2];
#pragma unroll
    for (int i = 0; i < 2; i++) {
        int row = wm + i * 16 + (lane & 15);
        int ko  = (lane >> 4) * 8;
        a_addr[i] = sbase + (unsigned)(row * SMSH + ko) * 2;
    }
#pragma unroll
    for (int jp = 0; jp < 2; jp++) {
        int grp = lane >> 3, lr = lane & 7;
        int row = wn + jp * 16 + ((grp >> 1) * 8) + lr;
        int ko  = (grp & 1) * 8;
        b_addr[jp] = sbase + 2u * PANELB + (unsigned)(row * SMSH + ko) * 2;
    }

    float acc[2][4][4];
#pragma unroll
    for (int i = 0; i < 2; i++)
#pragma unroll
        for (int j = 0; j < 4; j++)
#pragma unroll
            for (int r = 0; r < 4; r++) acc[i][j][r] = 0.f;

    const int KT = K >> 6;

    auto load_stage = [&](int st, int kt) {
        const unsigned so = (unsigned)st * STAGE_D;
        const int kb = kt * 64;
#pragma unroll
        for (int j = 0; j < 4; j++) {
            cpa16(dsta[j] + so,          Ah + a_src[j] + kb, 16);
            cpa16(dsta[j] + so + PANELB, Al + a_src[j] + kb, 16);
        }
#pragma unroll
        for (int j = 0; j < 2; j++)
            cpa16(dstb[j] + so, Bw + b_src[j] + kb, 16);
        asm volatile("cp.async.commit_group;\n");
    };

    load_stage(0, 0);

    for (int kt = 0; kt < KT; kt++) {
        asm volatile("cp.async.wait_group 0;\n" ::: "memory");
        __syncthreads();

        if (kt + 1 < KT) load_stage((kt + 1) & 1, kt + 1);

        const unsigned so = (unsigned)(kt & 1) * STAGE_D;
#pragma unroll
        for (int ks = 0; ks < 4; ks++) {
            const unsigned kso = so + ks * 32;
            unsigned ah[2][4], al[2][4];
#pragma unroll
            for (int i = 0; i < 2; i++) {
                ldmx4(ah[i][0], ah[i][1], ah[i][2], ah[i][3], a_addr[i] + kso);
                ldmx4(al[i][0], al[i][1], al[i][2], al[i][3], a_addr[i] + kso + PANELB);
            }
#pragma unroll
            for (int jp = 0; jp < 2; jp++) {
                unsigned bw[2][2];
                ldmx4(bw[0][0], bw[0][1], bw[1][0], bw[1][1], b_addr[jp] + kso);
#pragma unroll
                for (int jj = 0; jj < 2; jj++) {
                    int j = jp * 2 + jj;
                    mma_f16(acc[0][j], ah[0], bw[jj]);
                    mma_f16(acc[1][j], ah[1], bw[jj]);
                }
#pragma unroll
                for (int jj = 0; jj < 2; jj++) {
                    int j = jp * 2 + jj;
                    mma_f16(acc[0][j], al[0], bw[jj]);
                    mma_f16(acc[1][j], al[1], bw[jj]);
                }
            }
        }
        __syncthreads();
    }

#pragma unroll
    for (int i = 0; i < 2; i++) {
        int r0 = bm + wm + i * 16 + (lane >> 2);
#pragma unroll
        for (int j = 0; j < 4; j++) {
            int col = wn + j * 8 + (lane & 3) * 2;
            float b0 = db[col], b1 = db[col + 1];
            {
                float v0 = gelu_exact(acc[i][j][0] + b0);
                float v1 = gelu_exact(acc[i][j][1] + b1);
                __half2 hv = __floats2half2_rn(v0, v1);
                *(__half2*)(Hout + (size_t)r0 * RAD_ + col) = hv;
            }
            {
                float v0 = gelu_exact(acc[i][j][2] + b0);
                float v1 = gelu_exact(acc[i][j][3] + b1);
                __half2 hv = __floats2half2_rn(v0, v1);
                *(__half2*)(Hout + (size_t)(r0 + 8) * RAD_ + col) = hv;
            }
        }
    }
}

// ---------------------------------------------------------------------------
// Adapter up-proj GEMM: out[M,1280] = X + ( H[M,64] @ uW[1280,64]^T + ub )
// ---------------------------------------------------------------------------
__global__ void __launch_bounds__(256, 2) adapter_up_kernel(
    const fp16* __restrict__ Hbuf,
    const fp16* __restrict__ uw0, const fp16* __restrict__ uw1,
    const float* __restrict__ ub0, const float* __restrict__ ub1,
    const fp16* __restrict__ F0h, const fp16* __restrict__ F0l,
    const fp16* __restrict__ F1h, const fp16* __restrict__ F1l,
    float* __restrict__ out)
{
    __shared__ fp16 smem_up[2 * 128 * SMSH];
    const unsigned sbase = smem_u32(smem_up);

    const int z = blockIdx.z;
    const fp16* A  = Hbuf + (size_t)z * M_BS * RAD_;
    const fp16* Bw = z ? uw1 : uw0;
    const float* ub = z ? ub1 : ub0;
    const fp16* Fh = z ? F1h : F0h;
    const fp16* Fl = z ? F1l : F0l;
    float* C = out + (size_t)(z + 1) * OFF_;

    const int tid  = threadIdx.x;
    const int warp = tid >> 5;
    const int lane = tid & 31;
    const int bm = blockIdx.y * 128;
    const int bn = blockIdx.x * 128;

#pragma unroll
    for (int j = 0; j < 4; j++) {
        int c   = tid + 256 * j;
        int row = c >> 3;
        int sl  = c & 7;
        *(uint4*)(smem_up + row * SMSH + sl * 8) =
            *(const uint4*)(A + (size_t)(bm + row) * RAD_ + sl * 8);
        *(uint4*)(smem_up + 128 * SMSH + row * SMSH + sl * 8) =
            *(const uint4*)(Bw + (size_t)(bn + row) * RAD_ + sl * 8);
    }
    __syncthreads();

    const int wm = (warp >> 1) * 32;
    const int wn = (warp & 1) * 64;

    unsigned a_addr[2], b_addr[4];
#pragma unroll
    for (int i = 0; i < 2; i++) {
        int row = wm + i * 16 + (lane & 15);
        int ko  = (lane >> 4) * 8;
        a_addr[i] = sbase + (unsigned)(row * SMSH + ko) * 2;
    }
#pragma unroll
    for (int jp = 0; jp < 4; jp++) {
        int grp = lane >> 3, lr = lane & 7;
        int row = wn + jp * 16 + ((grp >> 1) * 8) + lr;
        int ko  = (grp & 1) * 8;
        b_addr[jp] = sbase + (unsigned)(128 * SMSH + row * SMSH + ko) * 2;
    }

    float acc[2][8][4];
#pragma unroll
    for (int i = 0; i < 2; i++)
#pragma unroll
        for (int j = 0; j < 8; j++)
#pragma unroll
            for (int r = 0; r < 4; r++) acc[i][j][r] = 0.f;

#pragma unroll
    for (int ks = 0; ks < 4; ks++) {
        const unsigned kso = ks * 32;
        unsigned ah[2][4];
#pragma unroll
        for (int i = 0; i < 2; i++)
            ldmx4(ah[i][0], ah[i][1], ah[i][2], ah[i][3], a_addr[i] + kso);
#pragma unroll
        for (int jp = 0; jp < 4; jp++) {
            unsigned bw[2][2];
            ldmx4(bw[0][0], bw[0][1], bw[1][0], bw[1][1], b_addr[jp] + kso);
#pragma unroll
            for (int jj = 0; jj < 2; jj++) {
                int j = jp * 2 + jj;
                mma_f16(acc[0][j], ah[0], bw[jj]);
                mma_f16(acc[1][j], ah[1], bw[jj]);
            }
        }
    }

#pragma unroll
    for (int i = 0; i < 2; i++) {
        int r0 = bm + wm + i * 16 + (lane >> 2);
#pragma unroll
        for (int j = 0; j < 8; j++) {
            int col = bn + wn + j * 8 + (lane & 3) * 2;
            float u0 = ub[col], u1 = ub[col + 1];
#pragma unroll
            for (int rr = 0; rr < 2; rr++) {
                int r = r0 + rr * 8;
                __half2 xh = *(const __half2*)(Fh + (size_t)r * D_ + col);
                __half2 xl = *(const __half2*)(Fl + (size_t)r * D_ + col);
                float x0 = __half2float(__low2half(xh)) + __half2float(__low2half(xl));
                float x1 = __half2float(__high2half(xh)) + __half2float(__high2half(xl));
                float2 v = make_float2(acc[i][j][rr*2+0] + u0 + x0,
                                       acc[i][j][rr*2+1] + u1 + x1);
                *(float2*)(C + (size_t)r * D_ + col) = v;
            }
        }
    }
}

// ---------------------------------------------------------------------------
// Attention, 4-query batched: K/V rows loaded once per 4 queries, 4
// independent shfl-reduction chains per key -> 4x ILP on the latency chain.
// ---------------------------------------------------------------------------
template<int TKV>
__global__ void __launch_bounds__(256) attn_kernel_t(
    const float* __restrict__ q, const float* __restrict__ k,
    const float* __restrict__ v, const int* __restrict__ toks,
    int maybe64, fp16* __restrict__ outH, fp16* __restrict__ outL)
{
    constexpr int NS = (TKV + 31) / 32;
    extern __shared__ float sm[];
    float* Ks = sm;
    float* Vs = sm + TKV * HD_;

    const int b  = blockIdx.z;
    const int h  = blockIdx.y;
    const int s0 = blockIdx.x * 64;
    const int tid = threadIdx.x;

    int is64 = 0;
    if (toks && maybe64)
        is64 = (toks[1] == 0 && toks[3] == 0 && toks[5] == 0 && toks[7] == 0);

    if (toks) {
        for (int i = tid; i < TKV * HD_; i += 256) {
            int t = i / HD_;
            int d = i - t * HD_;
            int trow = is64 ? toks[2 * t] : toks[t];
            size_t gidx = ((size_t)b * T_ + trow) * D_ + h * HD_ + d;
            Ks[i] = k[gidx];
            Vs[i] = v[gidx];
        }
    } else {
        const float* kb = k + (size_t)b * T_ * D_ + h * HD_;
        const float* vb = v + (size_t)b * T_ * D_ + h * HD_;
        for (int i = tid * 4; i < TKV * HD_; i += 1024) {
            int t = i / HD_;
            int d = i - t * HD_;
            *(float4*)(Ks + i) = *(const float4*)(kb + (size_t)t * D_ + d);
            *(float4*)(Vs + i) = *(const float4*)(vb + (size_t)t * D_ + d);
        }
    }
    __syncthreads();

    const int warp = tid >> 5;
    const int lane = tid & 31;
    const float scale = 0.07905694150420949f;
    const unsigned FULL = 0xffffffffu;

#pragma unroll
    for (int g = 0; g < 2; g++) {
        const int s = s0 + warp * 8 + g * 4;   // 4 consecutive query rows
        size_t base0 = ((size_t)b * S_ + s) * D_ + h * HD_;

        float qr[4][5];
#pragma unroll
        for (int i = 0; i < 4; i++)
#pragma unroll
            for (int j = 0; j < 5; j++)
                qr[i][j] = q[base0 + (size_t)i * D_ + lane + 32 * j];

        float sc[4][NS];
#pragma unroll
        for (int i = 0; i < 4; i++)
#pragma unroll
            for (int n = 0; n < NS; n++) sc[i][n] = 0.f;

#pragma unroll 2
        for (int t = 0; t < TKV; t++) {
            const float* kr = Ks + t * HD_;
            float kv_[5];
#pragma unroll
            for (int j = 0; j < 5; j++) kv_[j] = kr[lane + 32 * j];

            float p[4];
#pragma unroll
            for (int i = 0; i < 4; i++) {
                p[i] = 0.f;
#pragma unroll
                for (int j = 0; j < 5; j++) p[i] += qr[i][j] * kv_[j];
            }
#pragma unroll
            for (int off = 16; off; off >>= 1) {
#pragma unroll
                for (int i = 0; i < 4; i++)
                    p[i] += __shfl_xor_sync(FULL, p[i], off);
            }
            if ((t & 31) == lane) {
#pragma unroll
                for (int i = 0; i < 4; i++) sc[i][t >> 5] = p[i] * scale;
            }
        }

        float m[4];
#pragma unroll
        for (int i = 0; i < 4; i++) {
            m[i] = -1e30f;
#pragma unroll
            for (int n = 0; n < NS; n++)
                if (n * 32 + lane < TKV) m[i] = fmaxf(m[i], sc[i][n]);
        }
#pragma unroll
        for (int off = 16; off; off >>= 1) {
#pragma unroll
            for (int i = 0; i < 4; i++)
                m[i] = fmaxf(m[i], __shfl_xor_sync(FULL, m[i], off));
        }
        float ssum[4];
#pragma unroll
        for (int i = 0; i < 4; i++) {
            ssum[i] = 0.f;
#pragma unroll
            for (int n = 0; n < NS; n++) {
                sc[i][n] = (n * 32 + lane < TKV) ? expf(sc[i][n] - m[i]) : 0.f;
                ssum[i] += sc[i][n];
            }
        }
#pragma unroll
        for (int off = 16; off; off >>= 1) {
#pragma unroll
            for (int i = 0; i < 4; i++)
                ssum[i] += __shfl_xor_sync(FULL, ssum[i], off);
        }
#pragma unroll
        for (int i = 0; i < 4; i++) {
            float inv = 1.f / ssum[i];
#pragma unroll
            for (int n = 0; n < NS; n++) sc[i][n] *= inv;
        }

        float o[4][5];
#pragma unroll
        for (int i = 0; i < 4; i++)
#pragma unroll
            for (int j = 0; j < 5; j++) o[i][j] = 0.f;

#pragma unroll 2
        for (int t = 0; t < TKV; t++) {
            const float* vr = Vs + t * HD_;
            float vv[5];
#pragma unroll
            for (int j = 0; j < 5; j++) vv[j] = vr[lane + 32 * j];
            float p[4];
#pragma unroll
            for (int i = 0; i < 4; i++)
                p[i] = __shfl_sync(FULL, sc[i][t >> 5], t & 31);
#pragma unroll
            for (int i = 0; i < 4; i++)
#pragma unroll
                for (int j = 0; j < 5; j++) o[i][j] += p[i] * vv[j];
        }

#pragma unroll
        for (int i = 0; i < 4; i++) {
#pragma unroll
            for (int j = 0; j < 5; j++) {
                fp16 hh, ll; split_f16(o[i][j], hh, ll);
                outH[base0 + (size_t)i * D_ + lane + 32 * j] = hh;
                outL[base0 + (size_t)i * D_ + lane + 32 * j] = ll;
            }
        }
    }
}

// ---------------------------------------------------------------------------
// Launch
// ---------------------------------------------------------------------------
extern "C" void kernel_launch(void* const* d_in, const int* in_sizes, int n_in,
                              void* d_out, int out_size)
{
    const float* hs    = (const float*)d_in[0];
    const float* enc   = (const float*)d_in[1];
    const int*   e0    = (const int*)  d_in[2];
    const int*   e1    = (const int*)  d_in[3];
    const float* Wq    = (const float*)d_in[4];
    const float* Wk    = (const float*)d_in[5];
    const float* Wv    = (const float*)d_in[6];
    const float* Wo    = (const float*)d_in[7];
    const float* bo    = (const float*)d_in[8];
    const float* lkA   = (const float*)d_in[9];
    const float* lkB   = (const float*)d_in[10];
    const float* lvA   = (const float*)d_in[11];
    const float* lvB   = (const float*)d_in[12];
    const float* loA   = (const float*)d_in[13];
    const float* loB   = (const float*)d_in[14];
    const float* a0dW  = (const float*)d_in[15];
    const float* a0db  = (const float*)d_in[16];
    const float* a0uW  = (const float*)d_in[17];
    const float* a0ub  = (const float*)d_in[18];
    const float* a1dW  = (const float*)d_in[19];
    const float* a1db  = (const float*)d_in[20];
    const float* a1uW  = (const float*)d_in[21];
    const float* a1ub  = (const float*)d_in[22];

    float *qp, *kp, *vp;
    fp16 *hsh, *hsl, *fgh, *fgl, *f0h, *f0l, *f1h, *f1l, *ench, *encl;
    fp16 *wq, *wo, *wk, *wv, *dw0, *dw1, *uw0, *uw1, *Hb;
    cudaGetSymbolAddress((void**)&qp,   g_q);
    cudaGetSymbolAddress((void**)&kp,   g_k);
    cudaGetSymbolAddress((void**)&vp,   g_v);
    cudaGetSymbolAddress((void**)&hsh,  g_hs_hi);
    cudaGetSymbolAddress((void**)&hsl,  g_hs_lo);
    cudaGetSymbolAddress((void**)&fgh,  g_fg_hi);
    cudaGetSymbolAddress((void**)&fgl,  g_fg_lo);
    cudaGetSymbolAddress((void**)&f0h,  g_f0_hi);
    cudaGetSymbolAddress((void**)&f0l,  g_f0_lo);
    cudaGetSymbolAddress((void**)&f1h,  g_f1_hi);
    cudaGetSymbolAddress((void**)&f1l,  g_f1_lo);
    cudaGetSymbolAddress((void**)&ench, g_enc_hi);
    cudaGetSymbolAddress((void**)&encl, g_enc_lo);
    cudaGetSymbolAddress((void**)&wq,   g_wq);
    cudaGetSymbolAddress((void**)&wo,   g_wo);
    cudaGetSymbolAddress((void**)&wk,   g_wk);
    cudaGetSymbolAddress((void**)&wv,   g_wv);
    cudaGetSymbolAddress((void**)&dw0,  g_dw0);
    cudaGetSymbolAddress((void**)&dw1,  g_dw1);
    cudaGetSymbolAddress((void**)&uw0,  g_uw0);
    cudaGetSymbolAddress((void**)&uw1,  g_uw1);
    cudaGetSymbolAddress((void**)&Hb,   g_H);

    float* out = (float*)d_out;

    cudaFuncSetAttribute(mma_gemm_kernel,
                         cudaFuncAttributeMaxDynamicSharedMemorySize, GDYN);
    cudaFuncSetAttribute(adapter_down_kernel,
                         cudaFuncAttributeMaxDynamicSharedMemorySize, GDYN_D);
    cudaFuncSetAttribute(attn_kernel_t<77>,
                         cudaFuncAttributeMaxDynamicSharedMemorySize, 101376);

    // 1: fused prep (all converts + folds)
    long prep_blocks = (PREP_TOT + 255) / 256;
    prep_kernel<<<(unsigned)prep_blocks, 256>>>(
        hs, enc, Wq, a0dW, a1dW, a0uW, a1uW,
        Wk, lkA, lkB, Wv, lvA, lvB, Wo, loA, loB,
        hsh, hsl, ench, encl, wq, dw0, dw1, uw0, uw1, wk, wv, wo);

    // 2: q projection
    dim3 gq(D_ / 128, M_BS / 128, 1);
    mma_gemm_kernel<<<gq, 256, GDYN>>>(hsh, hsl, wq, nullptr, nullptr,
                                       qp, nullptr, M_BS, D_, D_);

    // 3: merged k+v projections
    dim3 gkv(D_ / 128, (M_BT + 127) / 128, 2);
    mma_gemm_kernel<<<gkv, 256, GDYN>>>(ench, encl, wk, wv, nullptr,
                                        kp, vp, M_BT, D_, DT_);

    // 4: global attention  <-- ncu capture slot
    dim3 ga(S_ / 64, H_, B_);
    attn_kernel_t<77><<<ga, 256, (size_t)T_ * HD_ * 2 * sizeof(float)>>>(
        qp, kp, vp, nullptr, 0, fgh, fgl);

    // 5-6: entity attentions
    attn_kernel_t<8><<<ga, 256, (size_t)8 * HD_ * 2 * sizeof(float)>>>(
        qp, kp, vp, e0, 1, f0h, f0l);
    attn_kernel_t<12><<<ga, 256, (size_t)12 * HD_ * 2 * sizeof(float)>>>(
        qp, kp, vp, e1, 0, f1h, f1l);

    // 7: adapter down (both adapters via z)
    dim3 gd(1, M_BS / 128, 2);
    adapter_down_kernel<<<gd, 256, GDYN_D>>>(f0h, f0l, f1h, f1l,
                                             dw0, dw1, a0db, a1db, Hb);

    // 8: adapter up (both adapters via z) -> F_0 / F_1 output slots
    dim3 gu(D_ / 128, M_BS / 128, 2);
    adapter_up_kernel<<<gu, 256>>>(Hb, uw0, uw1, a0ub, a1ub,
                                   f0h, f0l, f1h, f1l, out);

    // 9: output projection -> out slot
    mma_gemm_kernel<<<gq, 256, GDYN>>>(fgh, fgl, wo, nullptr, bo,
                                       out, nullptr, M_BS, D_, D_);
}